// round 1
// baseline (speedup 1.0000x reference)
#include <cuda_runtime.h>
#include <cuda_bf16.h>

// Problem constants
#define BB 2
#define TT 2048
#define DM 1024
#define NH 16
#define DH 64
#define MM (BB * TT)   // 4096

// Scratch (device globals; no allocation allowed)
__device__ float g_q[BB * NH * TT * DH];     // [B,H,T,Dh], rotary applied
__device__ float g_k[BB * NH * TT * DH];     // [B,H,T,Dh], rotary applied
__device__ float g_v[BB * NH * TT * DH];     // [B,H,T,Dh]
__device__ float g_att[BB * TT * DM];        // [B,T,D] attention output

// ---------------------------------------------------------------------------
// Tiled fp32 GEMM: out = X[M,1024] @ W[1024,1024]^T + bias
// mode 0: plain row-major out [M,1024]
// mode 1: head-split scatter to [B,H,T,Dh]
// mode 2: head-split scatter + rotate_half (pairs (x0,x1) -> (-x1, x0))
// Block: 64x64 tile, 256 threads, 4x4 micro-tile per thread.
// ---------------------------------------------------------------------------
__global__ void __launch_bounds__(256) gemm_kernel(
    const float* __restrict__ X, const float* __restrict__ W,
    const float* __restrict__ bias, float* __restrict__ out, int mode) {
  __shared__ __align__(16) float As[16][68];
  __shared__ __align__(16) float Bs[16][68];
  const int tid = threadIdx.x;
  const int tx = tid & 15, ty = tid >> 4;
  const int m0 = blockIdx.y * 64, n0 = blockIdx.x * 64;
  const int lr = tid >> 2;            // 0..63 (tile row)
  const int lc = (tid & 3) * 4;       // 0,4,8,12 (k chunk)
  const float* Xp = X + (size_t)(m0 + lr) * DM + lc;
  const float* Wp = W + (size_t)(n0 + lr) * DM + lc;

  float acc[4][4] = {};

  for (int k0 = 0; k0 < DM; k0 += 16) {
    float4 a4 = *reinterpret_cast<const float4*>(Xp + k0);
    float4 b4 = *reinterpret_cast<const float4*>(Wp + k0);
    __syncthreads();
    As[lc + 0][lr] = a4.x; As[lc + 1][lr] = a4.y;
    As[lc + 2][lr] = a4.z; As[lc + 3][lr] = a4.w;
    Bs[lc + 0][lr] = b4.x; Bs[lc + 1][lr] = b4.y;
    Bs[lc + 2][lr] = b4.z; Bs[lc + 3][lr] = b4.w;
    __syncthreads();
#pragma unroll
    for (int kk = 0; kk < 16; kk++) {
      float4 a = *reinterpret_cast<const float4*>(&As[kk][ty * 4]);
      float4 b = *reinterpret_cast<const float4*>(&Bs[kk][tx * 4]);
      float av[4] = {a.x, a.y, a.z, a.w};
      float bv[4] = {b.x, b.y, b.z, b.w};
#pragma unroll
      for (int i = 0; i < 4; i++)
#pragma unroll
        for (int j = 0; j < 4; j++) acc[i][j] = fmaf(av[i], bv[j], acc[i][j]);
    }
  }

  float bvv[4];
#pragma unroll
  for (int j = 0; j < 4; j++) bvv[j] = bias[n0 + tx * 4 + j];

#pragma unroll
  for (int i = 0; i < 4; i++) {
    int m = m0 + ty * 4 + i;
    float v0 = acc[i][0] + bvv[0];
    float v1 = acc[i][1] + bvv[1];
    float v2 = acc[i][2] + bvv[2];
    float v3 = acc[i][3] + bvv[3];
    float r0 = v0, r1 = v1, r2 = v2, r3 = v3;
    if (mode == 2) { r0 = -v1; r1 = v0; r2 = -v3; r3 = v2; }
    float4 o = make_float4(r0, r1, r2, r3);
    if (mode == 0) {
      *reinterpret_cast<float4*>(out + (size_t)m * DM + n0 + tx * 4) = o;
    } else {
      int b = m >> 11, t = m & (TT - 1);
      int n = n0 + tx * 4;
      int h = n >> 6, dh = n & (DH - 1);
      *reinterpret_cast<float4*>(out + (((size_t)(b * NH + h) * TT + t) * DH + dh)) = o;
    }
  }
}

// ---------------------------------------------------------------------------
// Flash-attention (fp32, online softmax), causal.
// grid = (T/64, B*H). Each block: 64 queries x full Dh=64.
// 256 threads, 4x4 micro-tiles for the 64x64 score tile and 64x64 O tile.
// Q pre-scaled by 1/sqrt(Dh). Causal handled by block loop bound + diag mask.
// Output scattered directly into [B,T,D] for the final projection.
// ---------------------------------------------------------------------------
__global__ void __launch_bounds__(256) attn_kernel(
    const float* __restrict__ Q, const float* __restrict__ K,
    const float* __restrict__ V, float* __restrict__ Out) {
  extern __shared__ __align__(16) float sm[];
  float* Qs = sm;                 // [d][row]  64x68
  float* Ks = Qs + 64 * 68;       // [d][col]  64x68
  float* Vs = Ks + 64 * 68;       // [key][d]  64x68
  float* Ps = Vs + 64 * 68;       // [key][row] 64x68

  const int tid = threadIdx.x;
  const int tx = tid & 15, ty = tid >> 4;
  const int qb = blockIdx.x, bh = blockIdx.y;

  const float* Qg = Q + ((size_t)bh * TT + qb * 64) * DH;

  for (int idx = tid; idx < 64 * 16; idx += 256) {
    int r = idx >> 4, c = (idx & 15) * 4;
    float4 v = *reinterpret_cast<const float4*>(Qg + r * DH + c);
    Qs[(c + 0) * 68 + r] = v.x * 0.125f;
    Qs[(c + 1) * 68 + r] = v.y * 0.125f;
    Qs[(c + 2) * 68 + r] = v.z * 0.125f;
    Qs[(c + 3) * 68 + r] = v.w * 0.125f;
  }

  float acc[4][4] = {};
  float mrow[4] = {-1e30f, -1e30f, -1e30f, -1e30f};
  float lrow[4] = {0.f, 0.f, 0.f, 0.f};

  for (int jb = 0; jb <= qb; jb++) {
    const float* Kg = K + ((size_t)bh * TT + jb * 64) * DH;
    const float* Vg = V + ((size_t)bh * TT + jb * 64) * DH;
    __syncthreads();  // previous PV done before overwriting K/V tiles
    for (int idx = tid; idx < 64 * 16; idx += 256) {
      int r = idx >> 4, c = (idx & 15) * 4;
      float4 kv = *reinterpret_cast<const float4*>(Kg + r * DH + c);
      Ks[(c + 0) * 68 + r] = kv.x;
      Ks[(c + 1) * 68 + r] = kv.y;
      Ks[(c + 2) * 68 + r] = kv.z;
      Ks[(c + 3) * 68 + r] = kv.w;
      float4 vv = *reinterpret_cast<const float4*>(Vg + r * DH + c);
      *reinterpret_cast<float4*>(&Vs[r * 68 + c]) = vv;
    }
    __syncthreads();

    // S = Q @ K^T  (64x64, 4x4 per thread)
    float s[4][4] = {};
#pragma unroll 8
    for (int d = 0; d < 64; d++) {
      float4 qa = *reinterpret_cast<const float4*>(&Qs[d * 68 + ty * 4]);
      float4 ka = *reinterpret_cast<const float4*>(&Ks[d * 68 + tx * 4]);
      float av[4] = {qa.x, qa.y, qa.z, qa.w};
      float bv[4] = {ka.x, ka.y, ka.z, ka.w};
#pragma unroll
      for (int i = 0; i < 4; i++)
#pragma unroll
        for (int j = 0; j < 4; j++) s[i][j] = fmaf(av[i], bv[j], s[i][j]);
    }

    if (jb == qb) {
#pragma unroll
      for (int i = 0; i < 4; i++)
#pragma unroll
        for (int j = 0; j < 4; j++)
          if (tx * 4 + j > ty * 4 + i) s[i][j] = -1e30f;
    }

    // Online softmax (row reduce across tx via xor-butterfly in warp)
#pragma unroll
    for (int i = 0; i < 4; i++) {
      float mx = fmaxf(fmaxf(s[i][0], s[i][1]), fmaxf(s[i][2], s[i][3]));
#pragma unroll
      for (int o = 8; o >= 1; o >>= 1)
        mx = fmaxf(mx, __shfl_xor_sync(0xffffffffu, mx, o));
      float mnew = fmaxf(mrow[i], mx);
      float corr = __expf(mrow[i] - mnew);
      mrow[i] = mnew;
      float rs = 0.f;
#pragma unroll
      for (int j = 0; j < 4; j++) {
        s[i][j] = __expf(s[i][j] - mnew);
        rs += s[i][j];
      }
#pragma unroll
      for (int o = 8; o >= 1; o >>= 1)
        rs += __shfl_xor_sync(0xffffffffu, rs, o);
      lrow[i] = lrow[i] * corr + rs;
#pragma unroll
      for (int j = 0; j < 4; j++) acc[i][j] *= corr;
    }

    // P -> smem transposed: Ps[key][row]
#pragma unroll
    for (int i = 0; i < 4; i++)
#pragma unroll
      for (int j = 0; j < 4; j++)
        Ps[(tx * 4 + j) * 68 + ty * 4 + i] = s[i][j];
    __syncthreads();

    // O += P @ V
#pragma unroll 8
    for (int kkey = 0; kkey < 64; kkey++) {
      float4 p = *reinterpret_cast<const float4*>(&Ps[kkey * 68 + ty * 4]);
      float4 v = *reinterpret_cast<const float4*>(&Vs[kkey * 68 + tx * 4]);
      float pv[4] = {p.x, p.y, p.z, p.w};
      float vv[4] = {v.x, v.y, v.z, v.w};
#pragma unroll
      for (int i = 0; i < 4; i++)
#pragma unroll
        for (int j = 0; j < 4; j++) acc[i][j] = fmaf(pv[i], vv[j], acc[i][j]);
    }
  }

  // Epilogue: normalize and scatter to [B,T,D]
  const int b = bh >> 4, h = bh & (NH - 1);
#pragma unroll
  for (int i = 0; i < 4; i++) {
    float inv = 1.0f / lrow[i];
    int t = qb * 64 + ty * 4 + i;
    float4 o = make_float4(acc[i][0] * inv, acc[i][1] * inv,
                           acc[i][2] * inv, acc[i][3] * inv);
    *reinterpret_cast<float4*>(
        Out + ((size_t)(b * TT + t)) * DM + h * DH + tx * 4) = o;
  }
}

extern "C" void kernel_launch(void* const* d_in, const int* in_sizes, int n_in,
                              void* d_out, int out_size) {
  const float* x  = (const float*)d_in[0];
  const float* Wq = (const float*)d_in[1];
  const float* bq = (const float*)d_in[2];
  const float* Wk = (const float*)d_in[3];
  const float* bk = (const float*)d_in[4];
  const float* Wv = (const float*)d_in[5];
  const float* bv = (const float*)d_in[6];
  const float* Wo = (const float*)d_in[7];
  const float* bo = (const float*)d_in[8];
  float* out = (float*)d_out;

  float *qp, *kp, *vp, *ap;
  cudaGetSymbolAddress((void**)&qp, g_q);
  cudaGetSymbolAddress((void**)&kp, g_k);
  cudaGetSymbolAddress((void**)&vp, g_v);
  cudaGetSymbolAddress((void**)&ap, g_att);

  static int smem_set = 0;
  const int attn_smem = 4 * 64 * 68 * (int)sizeof(float);  // 69632 B
  if (!smem_set) {
    cudaFuncSetAttribute(attn_kernel,
                         cudaFuncAttributeMaxDynamicSharedMemorySize, attn_smem);
    smem_set = 1;
  }

  dim3 gg(DM / 64, MM / 64);  // (16, 64)
  gemm_kernel<<<gg, 256>>>(x, Wq, bq, qp, 2);
  gemm_kernel<<<gg, 256>>>(x, Wk, bk, kp, 2);
  gemm_kernel<<<gg, 256>>>(x, Wv, bv, vp, 1);

  dim3 ga(TT / 64, BB * NH);  // (32, 32)
  attn_kernel<<<ga, 256, attn_smem>>>(qp, kp, vp, ap);

  gemm_kernel<<<gg, 256>>>(ap, Wo, bo, out, 0);
}

// round 2
// speedup vs baseline: 2.5280x; 2.5280x over previous
#include <cuda_runtime.h>
#include <cuda_bf16.h>

#define BB 2
#define TT 2048
#define DM 1024
#define NH 16
#define DH 64
#define MM (BB * TT)   // 4096

// Scratch (device globals; no allocation allowed)
__device__ float g_q[BB * NH * TT * DH];     // [B,H,T,Dh], rotary applied
__device__ float g_k[BB * NH * TT * DH];
__device__ float g_v[BB * NH * TT * DH];
__device__ float g_att[BB * TT * DM];        // [B,T,D]

__device__ __forceinline__ unsigned f2tf(float f) {
  unsigned u;
  asm("cvt.rna.tf32.f32 %0, %1;" : "=r"(u) : "f"(f));
  return u;
}

__device__ __forceinline__ void mma8(float* c, const unsigned* a,
                                     unsigned b0, unsigned b1) {
  asm("mma.sync.aligned.m16n8k8.row.col.f32.tf32.tf32.f32 "
      "{%0,%1,%2,%3},{%4,%5,%6,%7},{%8,%9},{%0,%1,%2,%3};"
      : "+f"(c[0]), "+f"(c[1]), "+f"(c[2]), "+f"(c[3])
      : "r"(a[0]), "r"(a[1]), "r"(a[2]), "r"(a[3]), "r"(b0), "r"(b1));
}

__device__ __forceinline__ uint4 pack_tf(float4 v) {
  return make_uint4(f2tf(v.x), f2tf(v.y), f2tf(v.z), f2tf(v.w));
}

// ---------------------------------------------------------------------------
// tf32 tensor-core GEMM: out = X[M,1024] @ W[1024,1024]^T + bias
// mode 0: row-major [M,1024]; mode 1: head-split [B,H,T,Dh];
// mode 2: head-split + rotate_half.
// Block 128x64, 8 warps (4m x 2n), warp tile 32x32, K-step 32.
// ---------------------------------------------------------------------------
__global__ void __launch_bounds__(256, 2) gemm_tf32(
    const float* __restrict__ X, const float* __restrict__ W,
    const float* __restrict__ bias, float* __restrict__ out, int mode) {
  extern __shared__ __align__(16) unsigned smu[];
  unsigned* Abuf = smu;                   // 2 x 128 x 36
  unsigned* Bbuf = smu + 2 * 128 * 36;    // 2 x 64 x 36

  const int tid = threadIdx.x;
  const int w = tid >> 5, lane = tid & 31;
  const int r = lane >> 2, c = lane & 3;
  const int m0 = (w >> 1) * 32, n0 = (w & 1) * 32;

  const int arow = tid >> 1, acol = (tid & 1) * 16;
  const int brow = tid >> 2, bcol = (tid & 3) * 8;

  const float* Xg = X + (size_t)(blockIdx.y * 128 + arow) * DM + acol;
  const float* Wg = W + (size_t)(blockIdx.x * 64 + brow) * DM + bcol;

  float acc[2][4][4] = {};
  float4 xa[4], wb[2];

  // preload k-step 0
#pragma unroll
  for (int i = 0; i < 4; i++) xa[i] = *reinterpret_cast<const float4*>(Xg + i * 4);
#pragma unroll
  for (int i = 0; i < 2; i++) wb[i] = *reinterpret_cast<const float4*>(Wg + i * 4);
#pragma unroll
  for (int i = 0; i < 4; i++)
    *reinterpret_cast<uint4*>(Abuf + arow * 36 + acol + i * 4) = pack_tf(xa[i]);
#pragma unroll
  for (int i = 0; i < 2; i++)
    *reinterpret_cast<uint4*>(Bbuf + brow * 36 + bcol + i * 4) = pack_tf(wb[i]);
  __syncthreads();

  for (int k0 = 0; k0 < 32; k0++) {
    const int cur = k0 & 1, nxt = cur ^ 1;
    if (k0 < 31) {
      const float* Xp = Xg + (k0 + 1) * 32;
      const float* Wp = Wg + (k0 + 1) * 32;
#pragma unroll
      for (int i = 0; i < 4; i++) xa[i] = *reinterpret_cast<const float4*>(Xp + i * 4);
#pragma unroll
      for (int i = 0; i < 2; i++) wb[i] = *reinterpret_cast<const float4*>(Wp + i * 4);
    }

    const unsigned* Ac = Abuf + cur * (128 * 36);
    const unsigned* Bc = Bbuf + cur * (64 * 36);
#pragma unroll
    for (int kc = 0; kc < 4; kc++) {
      unsigned a[2][4];
#pragma unroll
      for (int mi = 0; mi < 2; mi++) {
        const unsigned* ap = Ac + (m0 + 16 * mi + r) * 36 + kc * 8 + c;
        a[mi][0] = ap[0];
        a[mi][1] = ap[8 * 36];
        a[mi][2] = ap[4];
        a[mi][3] = ap[8 * 36 + 4];
      }
#pragma unroll
      for (int ni = 0; ni < 4; ni++) {
        const unsigned* bp = Bc + (n0 + 8 * ni + r) * 36 + kc * 8 + c;
        unsigned b0 = bp[0], b1 = bp[4];
#pragma unroll
        for (int mi = 0; mi < 2; mi++) mma8(acc[mi][ni], a[mi], b0, b1);
      }
    }

    if (k0 < 31) {
      unsigned* An = Abuf + nxt * (128 * 36);
      unsigned* Bn = Bbuf + nxt * (64 * 36);
#pragma unroll
      for (int i = 0; i < 4; i++)
        *reinterpret_cast<uint4*>(An + arow * 36 + acol + i * 4) = pack_tf(xa[i]);
#pragma unroll
      for (int i = 0; i < 2; i++)
        *reinterpret_cast<uint4*>(Bn + brow * 36 + bcol + i * 4) = pack_tf(wb[i]);
      __syncthreads();
    }
  }

  // Epilogue
  const int mbase = blockIdx.y * 128 + m0 + r;
  const int nbase = blockIdx.x * 64 + n0 + 2 * c;
#pragma unroll
  for (int ni = 0; ni < 4; ni++) {
    const int col = nbase + 8 * ni;
    const float b0 = bias[col], b1 = bias[col + 1];
#pragma unroll
    for (int mi = 0; mi < 2; mi++) {
#pragma unroll
      for (int half = 0; half < 2; half++) {
        const int row = mbase + 16 * mi + 8 * half;
        float v0 = acc[mi][ni][2 * half] + b0;
        float v1 = acc[mi][ni][2 * half + 1] + b1;
        float o0 = v0, o1 = v1;
        if (mode == 2) { o0 = -v1; o1 = v0; }
        float2 o = make_float2(o0, o1);
        if (mode == 0) {
          *reinterpret_cast<float2*>(out + (size_t)row * DM + col) = o;
        } else {
          int b_ = row >> 11, t = row & (TT - 1);
          int h = col >> 6, dh = col & (DH - 1);
          *reinterpret_cast<float2*>(
              out + (((size_t)(b_ * NH + h) * TT + t) * DH + dh)) = o;
        }
      }
    }
  }
}

// ---------------------------------------------------------------------------
// Flash attention with tf32 mma. 128-query tile, 64-key tiles, causal.
// 8 warps; warp w owns query rows 16w..16w+15. Q lives in A-fragments.
// ---------------------------------------------------------------------------
__global__ void __launch_bounds__(256, 2) attn_tf32(
    const float* __restrict__ Q, const float* __restrict__ K,
    const float* __restrict__ V, float* __restrict__ Out) {
  extern __shared__ __align__(16) unsigned sm[];
  unsigned* Ks = sm;                    // 64 x 68
  unsigned* Vs = sm + 64 * 68;          // 64 x 72
  unsigned* Ps = sm + 64 * 68 + 64 * 72;  // 128 x 68

  const int tid = threadIdx.x, w = tid >> 5, lane = tid & 31;
  const int r = lane >> 2, c = lane & 3;
  const int qb = gridDim.x - 1 - blockIdx.x;  // longest blocks first
  const int bh = blockIdx.y;

  // Q fragments (scaled by 1/sqrt(Dh))
  unsigned qa[8][4];
  const float* Qg = Q + ((size_t)bh * TT + qb * 128 + 16 * w) * DH;
#pragma unroll
  for (int kc = 0; kc < 8; kc++) {
    qa[kc][0] = f2tf(Qg[r * DH + kc * 8 + c] * 0.125f);
    qa[kc][1] = f2tf(Qg[(r + 8) * DH + kc * 8 + c] * 0.125f);
    qa[kc][2] = f2tf(Qg[r * DH + kc * 8 + c + 4] * 0.125f);
    qa[kc][3] = f2tf(Qg[(r + 8) * DH + kc * 8 + c + 4] * 0.125f);
  }

  float o[8][4] = {};
  float mrow[2] = {-1e30f, -1e30f}, lrow[2] = {0.f, 0.f};

  const int nkt = 2 * (qb + 1);
  for (int jt = 0; jt < nkt; jt++) {
    __syncthreads();
    const float* Kg = K + ((size_t)bh * TT + jt * 64) * DH;
    const float* Vg = V + ((size_t)bh * TT + jt * 64) * DH;
    for (int idx = tid; idx < 64 * 16; idx += 256) {
      int row = idx >> 4, col = (idx & 15) * 4;
      float4 kv = *reinterpret_cast<const float4*>(Kg + row * DH + col);
      *reinterpret_cast<uint4*>(Ks + row * 68 + col) = pack_tf(kv);
      float4 vv = *reinterpret_cast<const float4*>(Vg + row * DH + col);
      *reinterpret_cast<uint4*>(Vs + row * 72 + col) = pack_tf(vv);
    }
    __syncthreads();

    // S = Q @ K^T
    float s[8][4] = {};
#pragma unroll
    for (int kc = 0; kc < 8; kc++) {
#pragma unroll
      for (int ni = 0; ni < 8; ni++) {
        const unsigned* bp = Ks + (8 * ni + r) * 68 + kc * 8 + c;
        mma8(s[ni], qa[kc], bp[0], bp[4]);
      }
    }

    // causal mask (only tiles touching the diagonal)
    if (jt >= 2 * qb) {
      const int qrow0 = qb * 128 + 16 * w + r;
#pragma unroll
      for (int ni = 0; ni < 8; ni++) {
        const int key0 = jt * 64 + 8 * ni + 2 * c;
#pragma unroll
        for (int reg = 0; reg < 4; reg++) {
          int key = key0 + (reg & 1);
          int qr = qrow0 + 8 * (reg >> 1);
          if (key > qr) s[ni][reg] = -1e30f;
        }
      }
    }

    // online softmax (rows split over lane quad; shfl_xor 1,2 reduces)
#pragma unroll
    for (int h = 0; h < 2; h++) {
      float mx = -1e30f;
#pragma unroll
      for (int ni = 0; ni < 8; ni++)
        mx = fmaxf(mx, fmaxf(s[ni][2 * h], s[ni][2 * h + 1]));
      mx = fmaxf(mx, __shfl_xor_sync(0xffffffffu, mx, 1));
      mx = fmaxf(mx, __shfl_xor_sync(0xffffffffu, mx, 2));
      float mnew = fmaxf(mrow[h], mx);
      float corr = __expf(mrow[h] - mnew);
      mrow[h] = mnew;
      float rs = 0.f;
#pragma unroll
      for (int ni = 0; ni < 8; ni++) {
        s[ni][2 * h] = __expf(s[ni][2 * h] - mnew);
        s[ni][2 * h + 1] = __expf(s[ni][2 * h + 1] - mnew);
        rs += s[ni][2 * h] + s[ni][2 * h + 1];
      }
      rs += __shfl_xor_sync(0xffffffffu, rs, 1);
      rs += __shfl_xor_sync(0xffffffffu, rs, 2);
      lrow[h] = lrow[h] * corr + rs;
#pragma unroll
      for (int ni = 0; ni < 8; ni++) {
        o[ni][2 * h] *= corr;
        o[ni][2 * h + 1] *= corr;
      }
    }

    // P -> smem (warp-private rows), then PV mma
    {
      const int prow = 16 * w + r;
#pragma unroll
      for (int ni = 0; ni < 8; ni++) {
        const int col = 8 * ni + 2 * c;
        Ps[prow * 68 + col] = f2tf(s[ni][0]);
        Ps[prow * 68 + col + 1] = f2tf(s[ni][1]);
        Ps[(prow + 8) * 68 + col] = f2tf(s[ni][2]);
        Ps[(prow + 8) * 68 + col + 1] = f2tf(s[ni][3]);
      }
    }
    __syncwarp();
#pragma unroll
    for (int kc = 0; kc < 8; kc++) {
      unsigned pa[4];
      const unsigned* pp = Ps + (16 * w + r) * 68 + kc * 8 + c;
      pa[0] = pp[0];
      pa[1] = pp[8 * 68];
      pa[2] = pp[4];
      pa[3] = pp[8 * 68 + 4];
#pragma unroll
      for (int ni = 0; ni < 8; ni++) {
        const unsigned* vp = Vs + (kc * 8 + c) * 72 + 8 * ni + r;
        mma8(o[ni], pa, vp[0], vp[4 * 72]);
      }
    }
  }

  // epilogue: normalize, scatter to [B,T,D]
  const int b_ = bh >> 4, hh = bh & (NH - 1);
#pragma unroll
  for (int h = 0; h < 2; h++) {
    const float inv = 1.0f / lrow[h];
    const int t = qb * 128 + 16 * w + r + 8 * h;
#pragma unroll
    for (int ni = 0; ni < 8; ni++) {
      float2 ov = make_float2(o[ni][2 * h] * inv, o[ni][2 * h + 1] * inv);
      *reinterpret_cast<float2*>(
          Out + ((size_t)(b_ * TT + t)) * DM + hh * DH + 8 * ni + 2 * c) = ov;
    }
  }
}

extern "C" void kernel_launch(void* const* d_in, const int* in_sizes, int n_in,
                              void* d_out, int out_size) {
  const float* x  = (const float*)d_in[0];
  const float* Wq = (const float*)d_in[1];
  const float* bq = (const float*)d_in[2];
  const float* Wk = (const float*)d_in[3];
  const float* bk = (const float*)d_in[4];
  const float* Wv = (const float*)d_in[5];
  const float* bv = (const float*)d_in[6];
  const float* Wo = (const float*)d_in[7];
  const float* bo = (const float*)d_in[8];
  float* out = (float*)d_out;

  float *qp, *kp, *vp, *ap;
  cudaGetSymbolAddress((void**)&qp, g_q);
  cudaGetSymbolAddress((void**)&kp, g_k);
  cudaGetSymbolAddress((void**)&vp, g_v);
  cudaGetSymbolAddress((void**)&ap, g_att);

  const int gemm_smem = (2 * 128 * 36 + 2 * 64 * 36) * (int)sizeof(unsigned);  // 55296
  const int attn_smem = (64 * 68 + 64 * 72 + 128 * 68) * (int)sizeof(unsigned);  // 70656
  static int attr_set = 0;
  if (!attr_set) {
    cudaFuncSetAttribute(gemm_tf32,
                         cudaFuncAttributeMaxDynamicSharedMemorySize, gemm_smem);
    cudaFuncSetAttribute(attn_tf32,
                         cudaFuncAttributeMaxDynamicSharedMemorySize, attn_smem);
    attr_set = 1;
  }

  dim3 gg(DM / 64, MM / 128);  // (16, 32)
  gemm_tf32<<<gg, 256, gemm_smem>>>(x, Wq, bq, qp, 2);
  gemm_tf32<<<gg, 256, gemm_smem>>>(x, Wk, bk, kp, 2);
  gemm_tf32<<<gg, 256, gemm_smem>>>(x, Wv, bv, vp, 1);

  dim3 ga(TT / 128, BB * NH);  // (16, 32)
  attn_tf32<<<ga, 256, attn_smem>>>(qp, kp, vp, ap);

  gemm_tf32<<<gg, 256, gemm_smem>>>(ap, Wo, bo, out, 0);
}

// round 5
// speedup vs baseline: 3.6711x; 1.4522x over previous
#include <cuda_runtime.h>
#include <cstdint>

#define BB 2
#define TT 2048
#define DM 1024
#define NH 16
#define DH 64
#define MM (BB * TT)   // 4096

// Scratch (device globals; no allocation allowed)
__device__ float g_q[BB * NH * TT * DH];   // [B,H,T,Dh]
__device__ float g_k[BB * NH * TT * DH];   // [B,H,T,Dh]
__device__ float g_v[BB * NH * TT * DH];   // [B,H,T,Dh]
__device__ float g_att[MM * DM];           // attention out [B,T,D]
__device__ float g_attp[MM * DM];          // attention out packed-A frags
__device__ float g_xp[MM * DM];            // x packed-A frags (tf32)
__device__ float g_wp[4 * DM * DM];        // Wq,Wk,Wv,Wo packed-B frags

// ---------------------------------------------------------------------------
// helpers
// ---------------------------------------------------------------------------
__device__ __forceinline__ uint32_t smem_u32(const void* p) {
  uint32_t a;
  asm("{ .reg .u64 t; cvta.to.shared.u64 t, %1; cvt.u32.u64 %0, t; }"
      : "=r"(a) : "l"(p));
  return a;
}

__device__ __forceinline__ unsigned f2tf(float f) {
  unsigned u;
  asm("cvt.rna.tf32.f32 %0, %1;" : "=r"(u) : "f"(f));
  return u;
}

__device__ __forceinline__ void mma8(float* c, const unsigned* a,
                                     unsigned b0, unsigned b1) {
  asm("mma.sync.aligned.m16n8k8.row.col.f32.tf32.tf32.f32 "
      "{%0,%1,%2,%3},{%4,%5,%6,%7},{%8,%9},{%0,%1,%2,%3};"
      : "+f"(c[0]), "+f"(c[1]), "+f"(c[2]), "+f"(c[3])
      : "r"(a[0]), "r"(a[1]), "r"(a[2]), "r"(a[3]), "r"(b0), "r"(b1));
}

__device__ __forceinline__ uint4 pack_tf(float4 v) {
  return make_uint4(f2tf(v.x), f2tf(v.y), f2tf(v.z), f2tf(v.w));
}

#define CP_ASYNC16(dst, src) \
  asm volatile("cp.async.cg.shared.global [%0], [%1], 16;" :: "r"(dst), "l"(src))
#define CP_COMMIT() asm volatile("cp.async.commit_group;" ::: "memory")
#define CP_WAIT(n)  asm volatile("cp.async.wait_group %0;" :: "n"(n) : "memory")

// ---------------------------------------------------------------------------
// Packing into mma fragment order (tf32-rounded).
// A-frag chunk (m16 tile mt, k8 chunk kt), 128 floats at base
// (mt*128+kt)*128: value A[16m-tile row R][k8 col q] at lane*4+jj with
// lane = (R&7)*4 + (q&3), jj = (R>>3) + 2*(q>>2).
// B-frag chunk (n8 tile nt, k16 chunk kt2), 128 floats at (nt*64+kt2)*128:
// value W[8n-tile row r][k16 col q] at lane*4+jj, lane = r*4 + (q&3),
// jj = q>>2.
// ---------------------------------------------------------------------------
__global__ void pack_all(const float* __restrict__ x,
                         const float* __restrict__ Wq,
                         const float* __restrict__ Wk,
                         const float* __restrict__ Wv,
                         const float* __restrict__ Wo,
                         float* __restrict__ pX, float* __restrict__ pW) {
  const int z = blockIdx.z;
  const int idx0 = blockIdx.x * blockDim.x + threadIdx.x;
  const int stride = gridDim.x * blockDim.x;
  if (z == 0) {
    for (int idx = idx0; idx < MM * 256; idx += stride) {
      int m = idx >> 8, k4 = (idx & 255) * 4;
      float4 v = *(const float4*)(x + (size_t)m * DM + k4);
      int mt = m >> 4, R = m & 15, r_ = R & 7, hi = R >> 3;
      int kt = k4 >> 3, chi = (k4 >> 2) & 1;
      int j = hi + 2 * chi;
      float* d = pX + ((size_t)mt * 128 + kt) * 128 + r_ * 16 + j;
      d[0] = __uint_as_float(f2tf(v.x));
      d[4] = __uint_as_float(f2tf(v.y));
      d[8] = __uint_as_float(f2tf(v.z));
      d[12] = __uint_as_float(f2tf(v.w));
    }
  } else {
    const float* W = (z == 1) ? Wq : ((z == 2) ? Wk : ((z == 3) ? Wv : Wo));
    float* dst = pW + (size_t)(z - 1) * DM * DM;
    for (int idx = idx0; idx < DM * 256; idx += stride) {
      int n = idx >> 8, k4 = (idx & 255) * 4;
      float4 v = *(const float4*)(W + (size_t)n * DM + k4);
      int nt = n >> 3, r_ = n & 7, kt2 = k4 >> 4, j = (k4 >> 2) & 3;
      float* d = dst + ((size_t)nt * 64 + kt2) * 128 + r_ * 16 + j;
      d[0] = __uint_as_float(f2tf(v.x));
      d[4] = __uint_as_float(f2tf(v.y));
      d[8] = __uint_as_float(f2tf(v.z));
      d[12] = __uint_as_float(f2tf(v.w));
    }
  }
}

// Pack attention output [M, DM] -> packed-A fragment order (rounded).
__global__ void pack_attn(const float* __restrict__ src,
                          float* __restrict__ dst) {
  const int idx0 = blockIdx.x * blockDim.x + threadIdx.x;
  const int stride = gridDim.x * blockDim.x;
  for (int idx = idx0; idx < MM * 256; idx += stride) {
    int m = idx >> 8, k4 = (idx & 255) * 4;
    float4 v = *(const float4*)(src + (size_t)m * DM + k4);
    int mt = m >> 4, R = m & 15, r_ = R & 7, hi = R >> 3;
    int kt = k4 >> 3, chi = (k4 >> 2) & 1;
    int j = hi + 2 * chi;
    float* d = dst + ((size_t)mt * 128 + kt) * 128 + r_ * 16 + j;
    d[0] = __uint_as_float(f2tf(v.x));
    d[4] = __uint_as_float(f2tf(v.y));
    d[8] = __uint_as_float(f2tf(v.z));
    d[12] = __uint_as_float(f2tf(v.w));
  }
}

// ---------------------------------------------------------------------------
// GEMM on packed fragments: out = A[M,1024] @ W[1024,1024]^T + bias
// Block 128x128, 8 warps (2m x 4n), warp tile 64x32, k-step 16.
// 4-stage cp.async pipeline. modes: 0 plain [M,DM]; 1 head-split
// [B,H,T,Dh]; 2 head-split + rotate_half. Plain fp32 outputs.
// ---------------------------------------------------------------------------
#define GSTG 16384
#define GEMM_SMEM (4 * GSTG)

__global__ void __launch_bounds__(256, 2) gemm_pk(
    const float* __restrict__ pA,
    const float* __restrict__ pB0, const float* __restrict__ pB1,
    const float* __restrict__ pB2,
    const float* __restrict__ bi0, const float* __restrict__ bi1,
    const float* __restrict__ bi2,
    float* __restrict__ o0, float* __restrict__ o1, float* __restrict__ o2,
    int md0, int md1, int md2) {
  extern __shared__ __align__(16) char smem[];
  const int tid = threadIdx.x;
  const int w = tid >> 5, lane = tid & 31;
  const int r = lane >> 2, c = lane & 3;
  const int wm = w >> 2, wn = w & 3;
  const int z = blockIdx.z;
  const float* pB = (z == 0) ? pB0 : ((z == 1) ? pB1 : pB2);
  const float* bias = (z == 0) ? bi0 : ((z == 1) ? bi1 : bi2);
  float* out = (z == 0) ? o0 : ((z == 1) ? o1 : o2);
  const int mode = (z == 0) ? md0 : ((z == 1) ? md1 : md2);

  const float* Ab = pA + (size_t)blockIdx.y * 8 * 16384;
  const float* Bb = pB + (size_t)blockIdx.x * 16 * 8192;
  const uint32_t sb = smem_u32(smem);

  float acc[4][4][4] = {};

  auto load_iter = [&](int it, int s) {
    uint32_t sa = sb + s * GSTG;
#pragma unroll
    for (int i = 0; i < 2; i++) {
      int cid = tid + i * 256;
      int mt = cid >> 6, k2 = cid & 63;
      CP_ASYNC16(sa + cid * 16, Ab + (size_t)mt * 16384 + it * 256 + k2 * 4);
    }
#pragma unroll
    for (int i = 0; i < 2; i++) {
      int cid = tid + i * 256;
      int nt = cid >> 5, ln = cid & 31;
      CP_ASYNC16(sa + 8192 + cid * 16,
                 Bb + (size_t)nt * 8192 + it * 128 + ln * 4);
    }
    CP_COMMIT();
  };

  load_iter(0, 0);
  load_iter(1, 1);
  load_iter(2, 2);

  for (int it = 0; it < 64; it++) {
    CP_WAIT(2);
    __syncthreads();
    const int nx = it + 3;
    if (nx < 64) load_iter(nx, nx & 3); else CP_COMMIT();
    const char* st = smem + (it & 3) * GSTG;
    uint4 bfr[4];
#pragma unroll
    for (int n = 0; n < 4; n++)
      bfr[n] = *(const uint4*)(st + 8192 + ((wn * 4 + n) * 32 + lane) * 16);
#pragma unroll
    for (int ks = 0; ks < 2; ks++) {
      uint4 afr[4];
#pragma unroll
      for (int m = 0; m < 4; m++)
        afr[m] = *(const uint4*)(st + (((wm * 4 + m) * 2 + ks) * 32 + lane) * 16);
#pragma unroll
      for (int n = 0; n < 4; n++) {
        unsigned b0 = ks ? bfr[n].z : bfr[n].x;
        unsigned b1 = ks ? bfr[n].w : bfr[n].y;
#pragma unroll
        for (int m = 0; m < 4; m++)
          mma8(acc[m][n], (const unsigned*)&afr[m], b0, b1);
      }
    }
  }

  // epilogue
#pragma unroll
  for (int m = 0; m < 4; m++) {
    const int row0 = blockIdx.y * 128 + (wm * 4 + m) * 16 + r;
#pragma unroll
    for (int n = 0; n < 4; n++) {
      const int col = blockIdx.x * 128 + (wn * 4 + n) * 8 + 2 * c;
      const float b0 = bias[col], b1 = bias[col + 1];
#pragma unroll
      for (int hf = 0; hf < 2; hf++) {
        const int row = row0 + 8 * hf;
        float v0 = acc[m][n][2 * hf] + b0;
        float v1 = acc[m][n][2 * hf + 1] + b1;
        float q0 = (mode == 2) ? -v1 : v0;
        float q1 = (mode == 2) ? v0 : v1;
        float2 o = make_float2(q0, q1);
        if (mode == 0) {
          *(float2*)(out + (size_t)row * DM + col) = o;
        } else {
          int b_ = row >> 11, t = row & (TT - 1);
          int h = col >> 6, dh = col & (DH - 1);
          *(float2*)(out + ((size_t)(b_ * NH + h) * TT + t) * DH + dh) = o;
        }
      }
    }
  }
}

// ---------------------------------------------------------------------------
// Flash attention with tf32 mma — VERBATIM from the round-2 passing kernel.
// 128-query tile, 64-key tiles, causal, online softmax, writes [B,T,D].
// ---------------------------------------------------------------------------
__global__ void __launch_bounds__(256, 2) attn_tf32(
    const float* __restrict__ Q, const float* __restrict__ K,
    const float* __restrict__ V, float* __restrict__ Out) {
  extern __shared__ __align__(16) unsigned sm[];
  unsigned* Ks = sm;                      // 64 x 68
  unsigned* Vs = sm + 64 * 68;            // 64 x 72
  unsigned* Ps = sm + 64 * 68 + 64 * 72;  // 128 x 68

  const int tid = threadIdx.x, w = tid >> 5, lane = tid & 31;
  const int r = lane >> 2, c = lane & 3;
  const int qb = gridDim.x - 1 - blockIdx.x;
  const int bh = blockIdx.y;

  unsigned qa[8][4];
  const float* Qg = Q + ((size_t)bh * TT + qb * 128 + 16 * w) * DH;
#pragma unroll
  for (int kc = 0; kc < 8; kc++) {
    qa[kc][0] = f2tf(Qg[r * DH + kc * 8 + c] * 0.125f);
    qa[kc][1] = f2tf(Qg[(r + 8) * DH + kc * 8 + c] * 0.125f);
    qa[kc][2] = f2tf(Qg[r * DH + kc * 8 + c + 4] * 0.125f);
    qa[kc][3] = f2tf(Qg[(r + 8) * DH + kc * 8 + c + 4] * 0.125f);
  }

  float o[8][4] = {};
  float mrow[2] = {-1e30f, -1e30f}, lrow[2] = {0.f, 0.f};

  const int nkt = 2 * (qb + 1);
  for (int jt = 0; jt < nkt; jt++) {
    __syncthreads();
    const float* Kg = K + ((size_t)bh * TT + jt * 64) * DH;
    const float* Vg = V + ((size_t)bh * TT + jt * 64) * DH;
    for (int idx = tid; idx < 64 * 16; idx += 256) {
      int row = idx >> 4, col = (idx & 15) * 4;
      float4 kv = *reinterpret_cast<const float4*>(Kg + row * DH + col);
      *reinterpret_cast<uint4*>(Ks + row * 68 + col) = pack_tf(kv);
      float4 vv = *reinterpret_cast<const float4*>(Vg + row * DH + col);
      *reinterpret_cast<uint4*>(Vs + row * 72 + col) = pack_tf(vv);
    }
    __syncthreads();

    float s[8][4] = {};
#pragma unroll
    for (int kc = 0; kc < 8; kc++) {
#pragma unroll
      for (int ni = 0; ni < 8; ni++) {
        const unsigned* bp = Ks + (8 * ni + r) * 68 + kc * 8 + c;
        mma8(s[ni], qa[kc], bp[0], bp[4]);
      }
    }

    if (jt >= 2 * qb) {
      const int qrow0 = qb * 128 + 16 * w + r;
#pragma unroll
      for (int ni = 0; ni < 8; ni++) {
        const int key0 = jt * 64 + 8 * ni + 2 * c;
#pragma unroll
        for (int reg = 0; reg < 4; reg++) {
          int key = key0 + (reg & 1);
          int qr = qrow0 + 8 * (reg >> 1);
          if (key > qr) s[ni][reg] = -1e30f;
        }
      }
    }

#pragma unroll
    for (int h = 0; h < 2; h++) {
      float mx = -1e30f;
#pragma unroll
      for (int ni = 0; ni < 8; ni++)
        mx = fmaxf(mx, fmaxf(s[ni][2 * h], s[ni][2 * h + 1]));
      mx = fmaxf(mx, __shfl_xor_sync(0xffffffffu, mx, 1));
      mx = fmaxf(mx, __shfl_xor_sync(0xffffffffu, mx, 2));
      float mnew = fmaxf(mrow[h], mx);
      float corr = __expf(mrow[h] - mnew);
      mrow[h] = mnew;
      float rs = 0.f;
#pragma unroll
      for (int ni = 0; ni < 8; ni++) {
        s[ni][2 * h] = __expf(s[ni][2 * h] - mnew);
        s[ni][2 * h + 1] = __expf(s[ni][2 * h + 1] - mnew);
        rs += s[ni][2 * h] + s[ni][2 * h + 1];
      }
      rs += __shfl_xor_sync(0xffffffffu, rs, 1);
      rs += __shfl_xor_sync(0xffffffffu, rs, 2);
      lrow[h] = lrow[h] * corr + rs;
#pragma unroll
      for (int ni = 0; ni < 8; ni++) {
        o[ni][2 * h] *= corr;
        o[ni][2 * h + 1] *= corr;
      }
    }

    {
      const int prow = 16 * w + r;
#pragma unroll
      for (int ni = 0; ni < 8; ni++) {
        const int col = 8 * ni + 2 * c;
        Ps[prow * 68 + col] = f2tf(s[ni][0]);
        Ps[prow * 68 + col + 1] = f2tf(s[ni][1]);
        Ps[(prow + 8) * 68 + col] = f2tf(s[ni][2]);
        Ps[(prow + 8) * 68 + col + 1] = f2tf(s[ni][3]);
      }
    }
    __syncwarp();
#pragma unroll
    for (int kc = 0; kc < 8; kc++) {
      unsigned pa[4];
      const unsigned* pp = Ps + (16 * w + r) * 68 + kc * 8 + c;
      pa[0] = pp[0];
      pa[1] = pp[8 * 68];
      pa[2] = pp[4];
      pa[3] = pp[8 * 68 + 4];
#pragma unroll
      for (int ni = 0; ni < 8; ni++) {
        const unsigned* vp = Vs + (kc * 8 + c) * 72 + 8 * ni + r;
        mma8(o[ni], pa, vp[0], vp[4 * 72]);
      }
    }
  }

  const int b_ = bh >> 4, hh = bh & (NH - 1);
#pragma unroll
  for (int h = 0; h < 2; h++) {
    const float inv = 1.0f / lrow[h];
    const int t = qb * 128 + 16 * w + r + 8 * h;
#pragma unroll
    for (int ni = 0; ni < 8; ni++) {
      float2 ov = make_float2(o[ni][2 * h] * inv, o[ni][2 * h + 1] * inv);
      *reinterpret_cast<float2*>(
          Out + ((size_t)(b_ * TT + t)) * DM + hh * DH + 8 * ni + 2 * c) = ov;
    }
  }
}

extern "C" void kernel_launch(void* const* d_in, const int* in_sizes, int n_in,
                              void* d_out, int out_size) {
  const float* x  = (const float*)d_in[0];
  const float* Wq = (const float*)d_in[1];
  const float* bq = (const float*)d_in[2];
  const float* Wk = (const float*)d_in[3];
  const float* bk = (const float*)d_in[4];
  const float* Wv = (const float*)d_in[5];
  const float* bv = (const float*)d_in[6];
  const float* Wo = (const float*)d_in[7];
  const float* bo = (const float*)d_in[8];
  float* out = (float*)d_out;

  float *qp, *kp, *vp, *at, *ap, *xp, *wp;
  cudaGetSymbolAddress((void**)&qp, g_q);
  cudaGetSymbolAddress((void**)&kp, g_k);
  cudaGetSymbolAddress((void**)&vp, g_v);
  cudaGetSymbolAddress((void**)&at, g_att);
  cudaGetSymbolAddress((void**)&ap, g_attp);
  cudaGetSymbolAddress((void**)&xp, g_xp);
  cudaGetSymbolAddress((void**)&wp, g_wp);

  const int attn_smem = (64 * 68 + 64 * 72 + 128 * 68) * (int)sizeof(unsigned);
  static int attr_set = 0;
  if (!attr_set) {
    cudaFuncSetAttribute(gemm_pk, cudaFuncAttributeMaxDynamicSharedMemorySize,
                         GEMM_SMEM);
    cudaFuncSetAttribute(attn_tf32, cudaFuncAttributeMaxDynamicSharedMemorySize,
                         attn_smem);
    attr_set = 1;
  }

  const size_t WSZ = (size_t)DM * DM;

  // 1) pack inputs into fragment layouts (tf32-rounded)
  pack_all<<<dim3(512, 1, 5), 256>>>(x, Wq, Wk, Wv, Wo, xp, wp);

  // 2) fused QKV projections on packed-fragment GEMM
  gemm_pk<<<dim3(8, 32, 3), 256, GEMM_SMEM>>>(
      xp, wp, wp + WSZ, wp + 2 * WSZ, bq, bk, bv, qp, kp, vp, 2, 2, 1);

  // 3) attention (round-2 kernel, verbatim) -> [B,T,D]
  attn_tf32<<<dim3(16, 32), 256, attn_smem>>>(qp, kp, vp, at);

  // 4) repack attention output into packed-A fragment order
  pack_attn<<<512, 256>>>(at, ap);

  // 5) output projection
  gemm_pk<<<dim3(8, 32, 1), 256, GEMM_SMEM>>>(
      ap, wp + 3 * WSZ, wp + 3 * WSZ, wp + 3 * WSZ, bo, bo, bo, out, out, out,
      0, 0, 0);
}

// round 6
// speedup vs baseline: 4.0579x; 1.1053x over previous
#include <cuda_runtime.h>
#include <cstdint>

#define BB 2
#define TT 2048
#define DM 1024
#define NH 16
#define DH 64
#define MM (BB * TT)   // 4096

// Scratch (device globals; no allocation allowed)
__device__ float g_q[BB * NH * TT * DH];   // [B,H,T,Dh], tf32, *0.125*log2e
__device__ float g_k[BB * NH * TT * DH];   // [B,H,T,Dh], tf32
__device__ float g_v[BB * NH * TT * DH];   // [B,H,T,Dh], tf32
__device__ float g_attp[MM * DM];          // attention out, packed-A frags
__device__ float g_xp[MM * DM];            // x packed-A frags (tf32)
__device__ float g_wp[4 * DM * DM];        // Wq,Wk,Wv,Wo packed-B frags

// ---------------------------------------------------------------------------
// helpers
// ---------------------------------------------------------------------------
__device__ __forceinline__ uint32_t smem_u32(const void* p) {
  uint32_t a;
  asm("{ .reg .u64 t; cvta.to.shared.u64 t, %1; cvt.u32.u64 %0, t; }"
      : "=r"(a) : "l"(p));
  return a;
}

__device__ __forceinline__ unsigned f2tf(float f) {
  unsigned u;
  asm("cvt.rna.tf32.f32 %0, %1;" : "=r"(u) : "f"(f));
  return u;
}

__device__ __forceinline__ void mma8(float* c, const unsigned* a,
                                     unsigned b0, unsigned b1) {
  asm("mma.sync.aligned.m16n8k8.row.col.f32.tf32.tf32.f32 "
      "{%0,%1,%2,%3},{%4,%5,%6,%7},{%8,%9},{%0,%1,%2,%3};"
      : "+f"(c[0]), "+f"(c[1]), "+f"(c[2]), "+f"(c[3])
      : "r"(a[0]), "r"(a[1]), "r"(a[2]), "r"(a[3]), "r"(b0), "r"(b1));
}

#define CP_ASYNC16(dst, src) \
  asm volatile("cp.async.cg.shared.global [%0], [%1], 16;" :: "r"(dst), "l"(src))
#define CP_COMMIT() asm volatile("cp.async.commit_group;" ::: "memory")
#define CP_WAIT(n)  asm volatile("cp.async.wait_group %0;" :: "n"(n) : "memory")

// ---------------------------------------------------------------------------
// Packing into mma fragment order (tf32-rounded).  [same as R5 — proven]
// ---------------------------------------------------------------------------
__global__ void pack_all(const float* __restrict__ x,
                         const float* __restrict__ Wq,
                         const float* __restrict__ Wk,
                         const float* __restrict__ Wv,
                         const float* __restrict__ Wo,
                         float* __restrict__ pX, float* __restrict__ pW) {
  const int z = blockIdx.z;
  const int idx0 = blockIdx.x * blockDim.x + threadIdx.x;
  const int stride = gridDim.x * blockDim.x;
  if (z == 0) {
    for (int idx = idx0; idx < MM * 256; idx += stride) {
      int m = idx >> 8, k4 = (idx & 255) * 4;
      float4 v = *(const float4*)(x + (size_t)m * DM + k4);
      int mt = m >> 4, R = m & 15, r_ = R & 7, hi = R >> 3;
      int kt = k4 >> 3, chi = (k4 >> 2) & 1;
      int j = hi + 2 * chi;
      float* d = pX + ((size_t)mt * 128 + kt) * 128 + r_ * 16 + j;
      d[0] = __uint_as_float(f2tf(v.x));
      d[4] = __uint_as_float(f2tf(v.y));
      d[8] = __uint_as_float(f2tf(v.z));
      d[12] = __uint_as_float(f2tf(v.w));
    }
  } else {
    const float* W = (z == 1) ? Wq : ((z == 2) ? Wk : ((z == 3) ? Wv : Wo));
    float* dst = pW + (size_t)(z - 1) * DM * DM;
    for (int idx = idx0; idx < DM * 256; idx += stride) {
      int n = idx >> 8, k4 = (idx & 255) * 4;
      float4 v = *(const float4*)(W + (size_t)n * DM + k4);
      int nt = n >> 3, r_ = n & 7, kt2 = k4 >> 4, j = (k4 >> 2) & 3;
      float* d = dst + ((size_t)nt * 64 + kt2) * 128 + r_ * 16 + j;
      d[0] = __uint_as_float(f2tf(v.x));
      d[4] = __uint_as_float(f2tf(v.y));
      d[8] = __uint_as_float(f2tf(v.z));
      d[12] = __uint_as_float(f2tf(v.w));
    }
  }
}

// ---------------------------------------------------------------------------
// GEMM on packed fragments [R5 kernel + optional epilogue scale/round].
// Block 128x128, 8 warps (2m x 4n), 4-stage cp.async, k-step 16.
// modes: 0 plain [M,DM]; 1 head-split [B,H,T,Dh]; 2 head-split+rotate_half.
// rnd: round output to tf32 after multiplying by scale.
// ---------------------------------------------------------------------------
#define GSTG 16384
#define GEMM_SMEM (4 * GSTG)

__global__ void __launch_bounds__(256, 2) gemm_pk(
    const float* __restrict__ pA,
    const float* __restrict__ pB0, const float* __restrict__ pB1,
    const float* __restrict__ pB2,
    const float* __restrict__ bi0, const float* __restrict__ bi1,
    const float* __restrict__ bi2,
    float* __restrict__ o0, float* __restrict__ o1, float* __restrict__ o2,
    int md0, int md1, int md2, float sc0, float sc1, float sc2,
    int rn0, int rn1, int rn2) {
  extern __shared__ __align__(16) char smem[];
  const int tid = threadIdx.x;
  const int w = tid >> 5, lane = tid & 31;
  const int r = lane >> 2, c = lane & 3;
  const int wm = w >> 2, wn = w & 3;
  const int z = blockIdx.z;
  const float* pB = (z == 0) ? pB0 : ((z == 1) ? pB1 : pB2);
  const float* bias = (z == 0) ? bi0 : ((z == 1) ? bi1 : bi2);
  float* out = (z == 0) ? o0 : ((z == 1) ? o1 : o2);
  const int mode = (z == 0) ? md0 : ((z == 1) ? md1 : md2);
  const float scale = (z == 0) ? sc0 : ((z == 1) ? sc1 : sc2);
  const int rnd = (z == 0) ? rn0 : ((z == 1) ? rn1 : rn2);

  const float* Ab = pA + (size_t)blockIdx.y * 8 * 16384;
  const float* Bb = pB + (size_t)blockIdx.x * 16 * 8192;
  const uint32_t sb = smem_u32(smem);

  float acc[4][4][4] = {};

  auto load_iter = [&](int it, int s) {
    uint32_t sa = sb + s * GSTG;
#pragma unroll
    for (int i = 0; i < 2; i++) {
      int cid = tid + i * 256;
      int mt = cid >> 6, k2 = cid & 63;
      CP_ASYNC16(sa + cid * 16, Ab + (size_t)mt * 16384 + it * 256 + k2 * 4);
    }
#pragma unroll
    for (int i = 0; i < 2; i++) {
      int cid = tid + i * 256;
      int nt = cid >> 5, ln = cid & 31;
      CP_ASYNC16(sa + 8192 + cid * 16,
                 Bb + (size_t)nt * 8192 + it * 128 + ln * 4);
    }
    CP_COMMIT();
  };

  load_iter(0, 0);
  load_iter(1, 1);
  load_iter(2, 2);

  for (int it = 0; it < 64; it++) {
    CP_WAIT(2);
    __syncthreads();
    const int nx = it + 3;
    if (nx < 64) load_iter(nx, nx & 3); else CP_COMMIT();
    const char* st = smem + (it & 3) * GSTG;
    uint4 bfr[4];
#pragma unroll
    for (int n = 0; n < 4; n++)
      bfr[n] = *(const uint4*)(st + 8192 + ((wn * 4 + n) * 32 + lane) * 16);
#pragma unroll
    for (int ks = 0; ks < 2; ks++) {
      uint4 afr[4];
#pragma unroll
      for (int m = 0; m < 4; m++)
        afr[m] = *(const uint4*)(st + (((wm * 4 + m) * 2 + ks) * 32 + lane) * 16);
#pragma unroll
      for (int n = 0; n < 4; n++) {
        unsigned b0 = ks ? bfr[n].z : bfr[n].x;
        unsigned b1 = ks ? bfr[n].w : bfr[n].y;
#pragma unroll
        for (int m = 0; m < 4; m++)
          mma8(acc[m][n], (const unsigned*)&afr[m], b0, b1);
      }
    }
  }

  // epilogue
#pragma unroll
  for (int m = 0; m < 4; m++) {
    const int row0 = blockIdx.y * 128 + (wm * 4 + m) * 16 + r;
#pragma unroll
    for (int n = 0; n < 4; n++) {
      const int col = blockIdx.x * 128 + (wn * 4 + n) * 8 + 2 * c;
      const float b0 = bias[col], b1 = bias[col + 1];
#pragma unroll
      for (int hf = 0; hf < 2; hf++) {
        const int row = row0 + 8 * hf;
        float v0 = acc[m][n][2 * hf] + b0;
        float v1 = acc[m][n][2 * hf + 1] + b1;
        float q0 = (mode == 2) ? -v1 : v0;
        float q1 = (mode == 2) ? v0 : v1;
        if (rnd) {
          q0 = __uint_as_float(f2tf(q0 * scale));
          q1 = __uint_as_float(f2tf(q1 * scale));
        }
        float2 o = make_float2(q0, q1);
        if (mode == 0) {
          *(float2*)(out + (size_t)row * DM + col) = o;
        } else {
          int b_ = row >> 11, t = row & (TT - 1);
          int h = col >> 6, dh = col & (DH - 1);
          *(float2*)(out + ((size_t)(b_ * NH + h) * TT + t) * DH + dh) = o;
        }
      }
    }
  }
}

// ---------------------------------------------------------------------------
// Flash attention v3: tf32 mma, 128-query tile, 64-key tiles, causal.
// Q pre-scaled by 0.125*log2e and rounded; K/V pre-rounded (GEMM epilogue).
// Double-buffered cp.async K/V tiles (full fill: 16 segs/row!).
// exp2 softmax. Output written directly in packed-A fragment layout.
// smem: stage s at s*35840: Ks 64x272B, Vs 64x288B; Ps at 71680 (128x272B).
// ---------------------------------------------------------------------------
#define KVSTG 35840
#define PS_OFF 71680
#define ATTN_SMEM (2 * KVSTG + 34816)   // 106496

__global__ void __launch_bounds__(256, 2) attn3(
    const float* __restrict__ Q, const float* __restrict__ K,
    const float* __restrict__ V, float* __restrict__ pOut) {
  extern __shared__ __align__(16) char sm[];
  const uint32_t sb = smem_u32(sm);
  const int tid = threadIdx.x, w = tid >> 5, lane = tid & 31;
  const int r = lane >> 2, c = lane & 3;
  const int qb = gridDim.x - 1 - blockIdx.x;  // longest first
  const int bh = blockIdx.y;

  auto fill = [&](int jt, int s) {
    const float* Kg = K + ((size_t)bh * TT + jt * 64) * DH;
    const float* Vg = V + ((size_t)bh * TT + jt * 64) * DH;
    const uint32_t kb = sb + s * KVSTG;
    const uint32_t vb = kb + 17408;
#pragma unroll
    for (int i = 0; i < 4; i++) {
      int id = tid + i * 256;           // 0..1023
      int row = id >> 4, sc = id & 15;  // 64 rows x 16 segs
      CP_ASYNC16(kb + row * 272 + sc * 16, Kg + row * DH + sc * 4);
    }
#pragma unroll
    for (int i = 0; i < 4; i++) {
      int id = tid + i * 256;
      int row = id >> 4, sc = id & 15;
      CP_ASYNC16(vb + row * 288 + sc * 16, Vg + row * DH + sc * 4);
    }
    CP_COMMIT();
  };

  // Q fragments: raw loads (already tf32 + scaled)
  const unsigned* Qu =
      (const unsigned*)(Q + ((size_t)bh * TT + qb * 128 + 16 * w) * DH);
  unsigned qa[8][4];
#pragma unroll
  for (int kc = 0; kc < 8; kc++) {
    qa[kc][0] = Qu[r * DH + kc * 8 + c];
    qa[kc][1] = Qu[(r + 8) * DH + kc * 8 + c];
    qa[kc][2] = Qu[r * DH + kc * 8 + c + 4];
    qa[kc][3] = Qu[(r + 8) * DH + kc * 8 + c + 4];
  }

  float o[8][4] = {};
  float mrow[2] = {-1e30f, -1e30f}, lrow[2] = {0.f, 0.f};

  const int nkt = 2 * (qb + 1);
  fill(0, 0);

  for (int jt = 0; jt < nkt; jt++) {
    const int s = jt & 1;
    __syncthreads();  // buffer s^1 fully consumed by all warps (iter jt-1)
    if (jt + 1 < nkt) {
      fill(jt + 1, s ^ 1);
      CP_WAIT(1);  // tile jt's group done; jt+1's may be in flight
    } else {
      CP_WAIT(0);
    }
    __syncthreads();  // tile jt visible to all

    const char* kbuf = sm + s * KVSTG;
    const char* vbuf = kbuf + 17408;

    // S = Q @ K^T (log2 domain)
    float sacc[8][4] = {};
#pragma unroll
    for (int kc = 0; kc < 8; kc++) {
#pragma unroll
      for (int ni = 0; ni < 8; ni++) {
        const unsigned* bp =
            (const unsigned*)(kbuf + (8 * ni + r) * 272 + (kc * 8 + c) * 4);
        mma8(sacc[ni], qa[kc], bp[0], bp[4]);
      }
    }

    if (jt >= 2 * qb) {  // diagonal tiles: causal mask
      const int qrow0 = qb * 128 + 16 * w + r;
#pragma unroll
      for (int ni = 0; ni < 8; ni++) {
        const int key0 = jt * 64 + 8 * ni + 2 * c;
#pragma unroll
        for (int reg = 0; reg < 4; reg++) {
          int key = key0 + (reg & 1);
          int qr = qrow0 + 8 * (reg >> 1);
          if (key > qr) sacc[ni][reg] = -1e30f;
        }
      }
    }

    // online softmax (base-2)
#pragma unroll
    for (int h = 0; h < 2; h++) {
      float mx = -1e30f;
#pragma unroll
      for (int ni = 0; ni < 8; ni++)
        mx = fmaxf(mx, fmaxf(sacc[ni][2 * h], sacc[ni][2 * h + 1]));
      mx = fmaxf(mx, __shfl_xor_sync(0xffffffffu, mx, 1));
      mx = fmaxf(mx, __shfl_xor_sync(0xffffffffu, mx, 2));
      float mnew = fmaxf(mrow[h], mx);
      float corr = exp2f(mrow[h] - mnew);
      mrow[h] = mnew;
      float rs = 0.f;
#pragma unroll
      for (int ni = 0; ni < 8; ni++) {
        sacc[ni][2 * h] = exp2f(sacc[ni][2 * h] - mnew);
        sacc[ni][2 * h + 1] = exp2f(sacc[ni][2 * h + 1] - mnew);
        rs += sacc[ni][2 * h] + sacc[ni][2 * h + 1];
      }
      rs += __shfl_xor_sync(0xffffffffu, rs, 1);
      rs += __shfl_xor_sync(0xffffffffu, rs, 2);
      lrow[h] = lrow[h] * corr + rs;
#pragma unroll
      for (int ni = 0; ni < 8; ni++) {
        o[ni][2 * h] *= corr;
        o[ni][2 * h + 1] *= corr;
      }
    }

    // P -> smem (warp-private rows), then PV mma
    {
      const int prow = 16 * w + r;
#pragma unroll
      for (int ni = 0; ni < 8; ni++) {
        unsigned* p0 =
            (unsigned*)(sm + PS_OFF + prow * 272 + (8 * ni + 2 * c) * 4);
        unsigned* p1 =
            (unsigned*)(sm + PS_OFF + (prow + 8) * 272 + (8 * ni + 2 * c) * 4);
        p0[0] = f2tf(sacc[ni][0]);
        p0[1] = f2tf(sacc[ni][1]);
        p1[0] = f2tf(sacc[ni][2]);
        p1[1] = f2tf(sacc[ni][3]);
      }
    }
    __syncwarp();
#pragma unroll
    for (int kc = 0; kc < 8; kc++) {
      const unsigned* pp =
          (const unsigned*)(sm + PS_OFF + (16 * w + r) * 272 + (kc * 8 + c) * 4);
      unsigned pa[4];
      pa[0] = pp[0];
      pa[1] = pp[8 * 68];
      pa[2] = pp[4];
      pa[3] = pp[8 * 68 + 4];
#pragma unroll
      for (int ni = 0; ni < 8; ni++) {
        const unsigned* vp =
            (const unsigned*)(vbuf + (kc * 8 + c) * 288 + (8 * ni + r) * 4);
        mma8(o[ni], pa, vp[0], vp[4 * 72]);
      }
    }
  }

  // epilogue: normalize, round, write packed-A fragment layout
  const int b_ = bh >> 4, hh = bh & (NH - 1);
  const int mtile = b_ * 128 + qb * 8 + w;
#pragma unroll
  for (int h = 0; h < 2; h++) {
    const float inv = 1.0f / lrow[h];
#pragma unroll
    for (int ni = 0; ni < 8; ni++) {
      const int kt = hh * 8 + ni;
#pragma unroll
      for (int jp = 0; jp < 2; jp++) {
        int cc = 2 * c + jp;
        int cp = cc & 3, chi = cc >> 2;
        int jj = h + 2 * chi;
        size_t ad = ((size_t)mtile * 128 + kt) * 128 + (r * 4 + cp) * 4 + jj;
        pOut[ad] = __uint_as_float(f2tf(o[ni][2 * h + jp] * inv));
      }
    }
  }
}

extern "C" void kernel_launch(void* const* d_in, const int* in_sizes, int n_in,
                              void* d_out, int out_size) {
  const float* x  = (const float*)d_in[0];
  const float* Wq = (const float*)d_in[1];
  const float* bq = (const float*)d_in[2];
  const float* Wk = (const float*)d_in[3];
  const float* bk = (const float*)d_in[4];
  const float* Wv = (const float*)d_in[5];
  const float* bv = (const float*)d_in[6];
  const float* Wo = (const float*)d_in[7];
  const float* bo = (const float*)d_in[8];
  float* out = (float*)d_out;

  float *qp, *kp, *vp, *ap, *xp, *wp;
  cudaGetSymbolAddress((void**)&qp, g_q);
  cudaGetSymbolAddress((void**)&kp, g_k);
  cudaGetSymbolAddress((void**)&vp, g_v);
  cudaGetSymbolAddress((void**)&ap, g_attp);
  cudaGetSymbolAddress((void**)&xp, g_xp);
  cudaGetSymbolAddress((void**)&wp, g_wp);

  static int attr_set = 0;
  if (!attr_set) {
    cudaFuncSetAttribute(gemm_pk, cudaFuncAttributeMaxDynamicSharedMemorySize,
                         GEMM_SMEM);
    cudaFuncSetAttribute(attn3, cudaFuncAttributeMaxDynamicSharedMemorySize,
                         ATTN_SMEM);
    attr_set = 1;
  }

  const float QSCALE = 0.125f * 1.4426950408889634f;  // 1/sqrt(Dh) * log2(e)
  const size_t WSZ = (size_t)DM * DM;

  // 1) pack inputs into fragment layouts (tf32-rounded)
  pack_all<<<dim3(512, 1, 5), 256>>>(x, Wq, Wk, Wv, Wo, xp, wp);

  // 2) fused QKV projections; outputs rounded to tf32, Q pre-scaled
  gemm_pk<<<dim3(8, 32, 3), 256, GEMM_SMEM>>>(
      xp, wp, wp + WSZ, wp + 2 * WSZ, bq, bk, bv, qp, kp, vp,
      2, 2, 1, QSCALE, 1.f, 1.f, 1, 1, 1);

  // 3) attention -> packed-A fragments
  attn3<<<dim3(16, 32), 256, ATTN_SMEM>>>(qp, kp, vp, ap);

  // 4) output projection
  gemm_pk<<<dim3(8, 32, 1), 256, GEMM_SMEM>>>(
      ap, wp + 3 * WSZ, wp + 3 * WSZ, wp + 3 * WSZ, bo, bo, bo, out, out, out,
      0, 0, 0, 1.f, 1.f, 1.f, 0, 0, 0);
}

// round 7
// speedup vs baseline: 4.0888x; 1.0076x over previous
#include <cuda_runtime.h>
#include <cstdint>

#define BB 2
#define TT 2048
#define DM 1024
#define NH 16
#define DH 64
#define MM (BB * TT)   // 4096

// Scratch (device globals; no allocation allowed)
__device__ float g_q[BB * NH * TT * DH];   // [B,H,T,Dh], tf32, *0.125*log2e
__device__ float g_k[BB * NH * TT * DH];   // [B,H,T,Dh], tf32
__device__ float g_v[BB * NH * TT * DH];   // [B,H,T,Dh], tf32
__device__ float g_attp[MM * DM];          // attention out, packed-A frags
__device__ float g_xp[MM * DM];            // x packed-A frags (tf32)
__device__ float g_wp[4 * DM * DM];        // Wq,Wk,Wv,Wo packed-B frags

// ---------------------------------------------------------------------------
// helpers
// ---------------------------------------------------------------------------
__device__ __forceinline__ uint32_t smem_u32(const void* p) {
  uint32_t a;
  asm("{ .reg .u64 t; cvta.to.shared.u64 t, %1; cvt.u32.u64 %0, t; }"
      : "=r"(a) : "l"(p));
  return a;
}

__device__ __forceinline__ unsigned f2tf(float f) {
  unsigned u;
  asm("cvt.rna.tf32.f32 %0, %1;" : "=r"(u) : "f"(f));
  return u;
}

__device__ __forceinline__ void mma8(float* c, const unsigned* a,
                                     unsigned b0, unsigned b1) {
  asm("mma.sync.aligned.m16n8k8.row.col.f32.tf32.tf32.f32 "
      "{%0,%1,%2,%3},{%4,%5,%6,%7},{%8,%9},{%0,%1,%2,%3};"
      : "+f"(c[0]), "+f"(c[1]), "+f"(c[2]), "+f"(c[3])
      : "r"(a[0]), "r"(a[1]), "r"(a[2]), "r"(a[3]), "r"(b0), "r"(b1));
}

#define CP_ASYNC16(dst, src) \
  asm volatile("cp.async.cg.shared.global [%0], [%1], 16;" :: "r"(dst), "l"(src))
#define CP_COMMIT() asm volatile("cp.async.commit_group;" ::: "memory")
#define CP_WAIT(n)  asm volatile("cp.async.wait_group %0;" :: "n"(n) : "memory")

// ---------------------------------------------------------------------------
// Packing into mma fragment order (tf32-rounded).  [proven R5/R6]
// ---------------------------------------------------------------------------
__global__ void pack_all(const float* __restrict__ x,
                         const float* __restrict__ Wq,
                         const float* __restrict__ Wk,
                         const float* __restrict__ Wv,
                         const float* __restrict__ Wo,
                         float* __restrict__ pX, float* __restrict__ pW) {
  const int z = blockIdx.z;
  const int idx0 = blockIdx.x * blockDim.x + threadIdx.x;
  const int stride = gridDim.x * blockDim.x;
  if (z == 0) {
    for (int idx = idx0; idx < MM * 256; idx += stride) {
      int m = idx >> 8, k4 = (idx & 255) * 4;
      float4 v = *(const float4*)(x + (size_t)m * DM + k4);
      int mt = m >> 4, R = m & 15, r_ = R & 7, hi = R >> 3;
      int kt = k4 >> 3, chi = (k4 >> 2) & 1;
      int j = hi + 2 * chi;
      float* d = pX + ((size_t)mt * 128 + kt) * 128 + r_ * 16 + j;
      d[0] = __uint_as_float(f2tf(v.x));
      d[4] = __uint_as_float(f2tf(v.y));
      d[8] = __uint_as_float(f2tf(v.z));
      d[12] = __uint_as_float(f2tf(v.w));
    }
  } else {
    const float* W = (z == 1) ? Wq : ((z == 2) ? Wk : ((z == 3) ? Wv : Wo));
    float* dst = pW + (size_t)(z - 1) * DM * DM;
    for (int idx = idx0; idx < DM * 256; idx += stride) {
      int n = idx >> 8, k4 = (idx & 255) * 4;
      float4 v = *(const float4*)(W + (size_t)n * DM + k4);
      int nt = n >> 3, r_ = n & 7, kt2 = k4 >> 4, j = (k4 >> 2) & 3;
      float* d = dst + ((size_t)nt * 64 + kt2) * 128 + r_ * 16 + j;
      d[0] = __uint_as_float(f2tf(v.x));
      d[4] = __uint_as_float(f2tf(v.y));
      d[8] = __uint_as_float(f2tf(v.z));
      d[12] = __uint_as_float(f2tf(v.w));
    }
  }
}

// ---------------------------------------------------------------------------
// GEMM v3 on packed fragments: out = A[M,1024] @ W[1024,1024]^T + bias
// Block 128x128, 8 warps (2m x 4n), warp tile 64x32.
// k-step 32, 3-stage cp.async pipeline (32KB/stage) -> one sync per 64 HMMA.
// modes: 0 plain [M,DM]; 1 head-split [B,H,T,Dh]; 2 head-split+rotate_half.
// rnd: round output to tf32 after multiplying by scale.
// ---------------------------------------------------------------------------
#define GSTG 32768
#define GEMM_SMEM (3 * GSTG)   // 98304

__global__ void __launch_bounds__(256, 2) gemm_pk(
    const float* __restrict__ pA,
    const float* __restrict__ pB0, const float* __restrict__ pB1,
    const float* __restrict__ pB2,
    const float* __restrict__ bi0, const float* __restrict__ bi1,
    const float* __restrict__ bi2,
    float* __restrict__ o0, float* __restrict__ o1, float* __restrict__ o2,
    int md0, int md1, int md2, float sc0, float sc1, float sc2,
    int rn0, int rn1, int rn2) {
  extern __shared__ __align__(16) char smem[];
  const int tid = threadIdx.x;
  const int w = tid >> 5, lane = tid & 31;
  const int r = lane >> 2, c = lane & 3;
  const int wm = w >> 2, wn = w & 3;
  const int z = blockIdx.z;
  const float* pB = (z == 0) ? pB0 : ((z == 1) ? pB1 : pB2);
  const float* bias = (z == 0) ? bi0 : ((z == 1) ? bi1 : bi2);
  float* out = (z == 0) ? o0 : ((z == 1) ? o1 : o2);
  const int mode = (z == 0) ? md0 : ((z == 1) ? md1 : md2);
  const float scale = (z == 0) ? sc0 : ((z == 1) ? sc1 : sc2);
  const int rnd = (z == 0) ? rn0 : ((z == 1) ? rn1 : rn2);

  const float* Ab = pA + (size_t)blockIdx.y * 8 * 16384;
  const float* Bb = pB + (size_t)blockIdx.x * 16 * 8192;
  const uint32_t sb = smem_u32(smem);

  float acc[4][4][4] = {};

  // Load one k32 stage (A: 16KB = 8 mt x 2 k16 x 1KB; B: 16KB = 16 nt x 2 x 512B)
  auto load_iter = [&](int it, int s) {
    uint32_t sa = sb + s * GSTG;
    const int it2 = it * 2;
#pragma unroll
    for (int i = 0; i < 4; i++) {
      int cid = tid + i * 256;                 // 0..1023
      int mt = cid >> 7, itk = (cid >> 6) & 1, k2 = cid & 63;
      CP_ASYNC16(sa + cid * 16,
                 Ab + (size_t)mt * 16384 + (it2 + itk) * 256 + k2 * 4);
    }
#pragma unroll
    for (int i = 0; i < 4; i++) {
      int cid = tid + i * 256;                 // 0..1023
      int nt = cid >> 6, itk = (cid >> 5) & 1, ln = cid & 31;
      CP_ASYNC16(sa + 16384 + cid * 16,
                 Bb + (size_t)nt * 8192 + (it2 + itk) * 128 + ln * 4);
    }
    CP_COMMIT();
  };

  load_iter(0, 0);
  load_iter(1, 1);

  for (int it = 0; it < 32; it++) {
    CP_WAIT(1);
    __syncthreads();
    const int nx = it + 2;
    if (nx < 32) load_iter(nx, nx % 3); else CP_COMMIT();
    const char* st = smem + (it % 3) * GSTG;
#pragma unroll
    for (int itk = 0; itk < 2; itk++) {
      uint4 bfr[4];
#pragma unroll
      for (int n = 0; n < 4; n++)
        bfr[n] = *(const uint4*)(st + 16384 +
                                 ((((wn * 4 + n) * 2 + itk) * 32) + lane) * 16);
#pragma unroll
      for (int ks = 0; ks < 2; ks++) {
        uint4 afr[4];
#pragma unroll
        for (int m = 0; m < 4; m++)
          afr[m] = *(const uint4*)(st +
                   ((((wm * 4 + m) * 2 + itk) * 2 + ks) * 32 + lane) * 16);
#pragma unroll
        for (int n = 0; n < 4; n++) {
          unsigned b0 = ks ? bfr[n].z : bfr[n].x;
          unsigned b1 = ks ? bfr[n].w : bfr[n].y;
#pragma unroll
          for (int m = 0; m < 4; m++)
            mma8(acc[m][n], (const unsigned*)&afr[m], b0, b1);
        }
      }
    }
  }

  // epilogue
#pragma unroll
  for (int m = 0; m < 4; m++) {
    const int row0 = blockIdx.y * 128 + (wm * 4 + m) * 16 + r;
#pragma unroll
    for (int n = 0; n < 4; n++) {
      const int col = blockIdx.x * 128 + (wn * 4 + n) * 8 + 2 * c;
      const float b0 = bias[col], b1 = bias[col + 1];
#pragma unroll
      for (int hf = 0; hf < 2; hf++) {
        const int row = row0 + 8 * hf;
        float v0 = acc[m][n][2 * hf] + b0;
        float v1 = acc[m][n][2 * hf + 1] + b1;
        float q0 = (mode == 2) ? -v1 : v0;
        float q1 = (mode == 2) ? v0 : v1;
        if (rnd) {
          q0 = __uint_as_float(f2tf(q0 * scale));
          q1 = __uint_as_float(f2tf(q1 * scale));
        }
        float2 o = make_float2(q0, q1);
        if (mode == 0) {
          *(float2*)(out + (size_t)row * DM + col) = o;
        } else {
          int b_ = row >> 11, t = row & (TT - 1);
          int h = col >> 6, dh = col & (DH - 1);
          *(float2*)(out + ((size_t)(b_ * NH + h) * TT + t) * DH + dh) = o;
        }
      }
    }
  }
}

// ---------------------------------------------------------------------------
// Flash attention v3 (unchanged from R6 — proven at 405.8us total).
// ---------------------------------------------------------------------------
#define KVSTG 35840
#define PS_OFF 71680
#define ATTN_SMEM (2 * KVSTG + 34816)   // 106496

__global__ void __launch_bounds__(256, 2) attn3(
    const float* __restrict__ Q, const float* __restrict__ K,
    const float* __restrict__ V, float* __restrict__ pOut) {
  extern __shared__ __align__(16) char sm[];
  const uint32_t sb = smem_u32(sm);
  const int tid = threadIdx.x, w = tid >> 5, lane = tid & 31;
  const int r = lane >> 2, c = lane & 3;
  const int qb = gridDim.x - 1 - blockIdx.x;  // longest first
  const int bh = blockIdx.y;

  auto fill = [&](int jt, int s) {
    const float* Kg = K + ((size_t)bh * TT + jt * 64) * DH;
    const float* Vg = V + ((size_t)bh * TT + jt * 64) * DH;
    const uint32_t kb = sb + s * KVSTG;
    const uint32_t vb = kb + 17408;
#pragma unroll
    for (int i = 0; i < 4; i++) {
      int id = tid + i * 256;
      int row = id >> 4, sc = id & 15;
      CP_ASYNC16(kb + row * 272 + sc * 16, Kg + row * DH + sc * 4);
    }
#pragma unroll
    for (int i = 0; i < 4; i++) {
      int id = tid + i * 256;
      int row = id >> 4, sc = id & 15;
      CP_ASYNC16(vb + row * 288 + sc * 16, Vg + row * DH + sc * 4);
    }
    CP_COMMIT();
  };

  const unsigned* Qu =
      (const unsigned*)(Q + ((size_t)bh * TT + qb * 128 + 16 * w) * DH);
  unsigned qa[8][4];
#pragma unroll
  for (int kc = 0; kc < 8; kc++) {
    qa[kc][0] = Qu[r * DH + kc * 8 + c];
    qa[kc][1] = Qu[(r + 8) * DH + kc * 8 + c];
    qa[kc][2] = Qu[r * DH + kc * 8 + c + 4];
    qa[kc][3] = Qu[(r + 8) * DH + kc * 8 + c + 4];
  }

  float o[8][4] = {};
  float mrow[2] = {-1e30f, -1e30f}, lrow[2] = {0.f, 0.f};

  const int nkt = 2 * (qb + 1);
  fill(0, 0);

  for (int jt = 0; jt < nkt; jt++) {
    const int s = jt & 1;
    __syncthreads();
    if (jt + 1 < nkt) {
      fill(jt + 1, s ^ 1);
      CP_WAIT(1);
    } else {
      CP_WAIT(0);
    }
    __syncthreads();

    const char* kbuf = sm + s * KVSTG;
    const char* vbuf = kbuf + 17408;

    float sacc[8][4] = {};
#pragma unroll
    for (int kc = 0; kc < 8; kc++) {
#pragma unroll
      for (int ni = 0; ni < 8; ni++) {
        const unsigned* bp =
            (const unsigned*)(kbuf + (8 * ni + r) * 272 + (kc * 8 + c) * 4);
        mma8(sacc[ni], qa[kc], bp[0], bp[4]);
      }
    }

    if (jt >= 2 * qb) {
      const int qrow0 = qb * 128 + 16 * w + r;
#pragma unroll
      for (int ni = 0; ni < 8; ni++) {
        const int key0 = jt * 64 + 8 * ni + 2 * c;
#pragma unroll
        for (int reg = 0; reg < 4; reg++) {
          int key = key0 + (reg & 1);
          int qr = qrow0 + 8 * (reg >> 1);
          if (key > qr) sacc[ni][reg] = -1e30f;
        }
      }
    }

#pragma unroll
    for (int h = 0; h < 2; h++) {
      float mx = -1e30f;
#pragma unroll
      for (int ni = 0; ni < 8; ni++)
        mx = fmaxf(mx, fmaxf(sacc[ni][2 * h], sacc[ni][2 * h + 1]));
      mx = fmaxf(mx, __shfl_xor_sync(0xffffffffu, mx, 1));
      mx = fmaxf(mx, __shfl_xor_sync(0xffffffffu, mx, 2));
      float mnew = fmaxf(mrow[h], mx);
      float corr = exp2f(mrow[h] - mnew);
      mrow[h] = mnew;
      float rs = 0.f;
#pragma unroll
      for (int ni = 0; ni < 8; ni++) {
        sacc[ni][2 * h] = exp2f(sacc[ni][2 * h] - mnew);
        sacc[ni][2 * h + 1] = exp2f(sacc[ni][2 * h + 1] - mnew);
        rs += sacc[ni][2 * h] + sacc[ni][2 * h + 1];
      }
      rs += __shfl_xor_sync(0xffffffffu, rs, 1);
      rs += __shfl_xor_sync(0xffffffffu, rs, 2);
      lrow[h] = lrow[h] * corr + rs;
#pragma unroll
      for (int ni = 0; ni < 8; ni++) {
        o[ni][2 * h] *= corr;
        o[ni][2 * h + 1] *= corr;
      }
    }

    {
      const int prow = 16 * w + r;
#pragma unroll
      for (int ni = 0; ni < 8; ni++) {
        unsigned* p0 =
            (unsigned*)(sm + PS_OFF + prow * 272 + (8 * ni + 2 * c) * 4);
        unsigned* p1 =
            (unsigned*)(sm + PS_OFF + (prow + 8) * 272 + (8 * ni + 2 * c) * 4);
        p0[0] = f2tf(sacc[ni][0]);
        p0[1] = f2tf(sacc[ni][1]);
        p1[0] = f2tf(sacc[ni][2]);
        p1[1] = f2tf(sacc[ni][3]);
      }
    }
    __syncwarp();
#pragma unroll
    for (int kc = 0; kc < 8; kc++) {
      const unsigned* pp =
          (const unsigned*)(sm + PS_OFF + (16 * w + r) * 272 + (kc * 8 + c) * 4);
      unsigned pa[4];
      pa[0] = pp[0];
      pa[1] = pp[8 * 68];
      pa[2] = pp[4];
      pa[3] = pp[8 * 68 + 4];
#pragma unroll
      for (int ni = 0; ni < 8; ni++) {
        const unsigned* vp =
            (const unsigned*)(vbuf + (kc * 8 + c) * 288 + (8 * ni + r) * 4);
        mma8(o[ni], pa, vp[0], vp[4 * 72]);
      }
    }
  }

  const int b_ = bh >> 4, hh = bh & (NH - 1);
  const int mtile = b_ * 128 + qb * 8 + w;
#pragma unroll
  for (int h = 0; h < 2; h++) {
    const float inv = 1.0f / lrow[h];
#pragma unroll
    for (int ni = 0; ni < 8; ni++) {
      const int kt = hh * 8 + ni;
#pragma unroll
      for (int jp = 0; jp < 2; jp++) {
        int cc = 2 * c + jp;
        int cp = cc & 3, chi = cc >> 2;
        int jj = h + 2 * chi;
        size_t ad = ((size_t)mtile * 128 + kt) * 128 + (r * 4 + cp) * 4 + jj;
        pOut[ad] = __uint_as_float(f2tf(o[ni][2 * h + jp] * inv));
      }
    }
  }
}

extern "C" void kernel_launch(void* const* d_in, const int* in_sizes, int n_in,
                              void* d_out, int out_size) {
  const float* x  = (const float*)d_in[0];
  const float* Wq = (const float*)d_in[1];
  const float* bq = (const float*)d_in[2];
  const float* Wk = (const float*)d_in[3];
  const float* bk = (const float*)d_in[4];
  const float* Wv = (const float*)d_in[5];
  const float* bv = (const float*)d_in[6];
  const float* Wo = (const float*)d_in[7];
  const float* bo = (const float*)d_in[8];
  float* out = (float*)d_out;

  float *qp, *kp, *vp, *ap, *xp, *wp;
  cudaGetSymbolAddress((void**)&qp, g_q);
  cudaGetSymbolAddress((void**)&kp, g_k);
  cudaGetSymbolAddress((void**)&vp, g_v);
  cudaGetSymbolAddress((void**)&ap, g_attp);
  cudaGetSymbolAddress((void**)&xp, g_xp);
  cudaGetSymbolAddress((void**)&wp, g_wp);

  static int attr_set = 0;
  if (!attr_set) {
    cudaFuncSetAttribute(gemm_pk, cudaFuncAttributeMaxDynamicSharedMemorySize,
                         GEMM_SMEM);
    cudaFuncSetAttribute(attn3, cudaFuncAttributeMaxDynamicSharedMemorySize,
                         ATTN_SMEM);
    attr_set = 1;
  }

  const float QSCALE = 0.125f * 1.4426950408889634f;  // 1/sqrt(Dh) * log2(e)
  const size_t WSZ = (size_t)DM * DM;

  // 1) pack inputs into fragment layouts (tf32-rounded)
  pack_all<<<dim3(512, 1, 5), 256>>>(x, Wq, Wk, Wv, Wo, xp, wp);

  // 2) fused QKV projections; outputs rounded to tf32, Q pre-scaled
  gemm_pk<<<dim3(8, 32, 3), 256, GEMM_SMEM>>>(
      xp, wp, wp + WSZ, wp + 2 * WSZ, bq, bk, bv, qp, kp, vp,
      2, 2, 1, QSCALE, 1.f, 1.f, 1, 1, 1);

  // 3) attention -> packed-A fragments
  attn3<<<dim3(16, 32), 256, ATTN_SMEM>>>(qp, kp, vp, ap);

  // 4) output projection
  gemm_pk<<<dim3(8, 32, 1), 256, GEMM_SMEM>>>(
      ap, wp + 3 * WSZ, wp + 3 * WSZ, wp + 3 * WSZ, bo, bo, bo, out, out, out,
      0, 0, 0, 1.f, 1.f, 1.f, 0, 0, 0);
}

// round 8
// speedup vs baseline: 4.0983x; 1.0023x over previous
#include <cuda_runtime.h>
#include <cstdint>

#define BB 2
#define TT 2048
#define DM 1024
#define NH 16
#define DH 64
#define MM (BB * TT)   // 4096

// Scratch (device globals; no allocation allowed)
__device__ float g_q[BB * NH * TT * DH];   // [B,H,T,Dh], tf32, *0.125*log2e
__device__ float g_k[BB * NH * TT * DH];   // [B,H,T,Dh], tf32
__device__ float g_v[BB * NH * TT * DH];   // [B,H,T,Dh], tf32
__device__ float g_attp[MM * DM];          // attention out, packed-A frags
__device__ float g_xp[MM * DM];            // x packed-A frags (tf32)
__device__ float g_wp[4 * DM * DM];        // Wq,Wk,Wv,Wo packed-B frags

// ---------------------------------------------------------------------------
// helpers
// ---------------------------------------------------------------------------
__device__ __forceinline__ uint32_t smem_u32(const void* p) {
  uint32_t a;
  asm("{ .reg .u64 t; cvta.to.shared.u64 t, %1; cvt.u32.u64 %0, t; }"
      : "=r"(a) : "l"(p));
  return a;
}

__device__ __forceinline__ unsigned f2tf(float f) {
  unsigned u;
  asm("cvt.rna.tf32.f32 %0, %1;" : "=r"(u) : "f"(f));
  return u;
}

__device__ __forceinline__ void mma8(float* c, const unsigned* a,
                                     unsigned b0, unsigned b1) {
  asm("mma.sync.aligned.m16n8k8.row.col.f32.tf32.tf32.f32 "
      "{%0,%1,%2,%3},{%4,%5,%6,%7},{%8,%9},{%0,%1,%2,%3};"
      : "+f"(c[0]), "+f"(c[1]), "+f"(c[2]), "+f"(c[3])
      : "r"(a[0]), "r"(a[1]), "r"(a[2]), "r"(a[3]), "r"(b0), "r"(b1));
}

#define CP_ASYNC16(dst, src) \
  asm volatile("cp.async.cg.shared.global [%0], [%1], 16;" :: "r"(dst), "l"(src))
#define CP_COMMIT() asm volatile("cp.async.commit_group;" ::: "memory")
#define CP_WAIT(n)  asm volatile("cp.async.wait_group %0;" :: "n"(n) : "memory")

// ---------------------------------------------------------------------------
// Packing into mma fragment order (tf32-rounded).  [proven R5-R7]
// ---------------------------------------------------------------------------
__global__ void pack_all(const float* __restrict__ x,
                         const float* __restrict__ Wq,
                         const float* __restrict__ Wk,
                         const float* __restrict__ Wv,
                         const float* __restrict__ Wo,
                         float* __restrict__ pX, float* __restrict__ pW) {
  const int z = blockIdx.z;
  const int idx0 = blockIdx.x * blockDim.x + threadIdx.x;
  const int stride = gridDim.x * blockDim.x;
  if (z == 0) {
    for (int idx = idx0; idx < MM * 256; idx += stride) {
      int m = idx >> 8, k4 = (idx & 255) * 4;
      float4 v = *(const float4*)(x + (size_t)m * DM + k4);
      int mt = m >> 4, R = m & 15, r_ = R & 7, hi = R >> 3;
      int kt = k4 >> 3, chi = (k4 >> 2) & 1;
      int j = hi + 2 * chi;
      float* d = pX + ((size_t)mt * 128 + kt) * 128 + r_ * 16 + j;
      d[0] = __uint_as_float(f2tf(v.x));
      d[4] = __uint_as_float(f2tf(v.y));
      d[8] = __uint_as_float(f2tf(v.z));
      d[12] = __uint_as_float(f2tf(v.w));
    }
  } else {
    const float* W = (z == 1) ? Wq : ((z == 2) ? Wk : ((z == 3) ? Wv : Wo));
    float* dst = pW + (size_t)(z - 1) * DM * DM;
    for (int idx = idx0; idx < DM * 256; idx += stride) {
      int n = idx >> 8, k4 = (idx & 255) * 4;
      float4 v = *(const float4*)(W + (size_t)n * DM + k4);
      int nt = n >> 3, r_ = n & 7, kt2 = k4 >> 4, j = (k4 >> 2) & 3;
      float* d = dst + ((size_t)nt * 64 + kt2) * 128 + r_ * 16 + j;
      d[0] = __uint_as_float(f2tf(v.x));
      d[4] = __uint_as_float(f2tf(v.y));
      d[8] = __uint_as_float(f2tf(v.z));
      d[12] = __uint_as_float(f2tf(v.w));
    }
  }
}

// ---------------------------------------------------------------------------
// GEMM v4: block 128x128, 4 warps (2m x 2n), warp tile 64x64.
// Per k16 per warp: 16 LDS.128 for 64 HMMAs (ratio 4.0, was 2.67).
// k-step 32, 3-stage cp.async pipeline (32KB/stage).
// modes: 0 plain [M,DM]; 1 head-split [B,H,T,Dh]; 2 head-split+rotate_half.
// ---------------------------------------------------------------------------
#define GSTG 32768
#define GEMM_SMEM (3 * GSTG)   // 98304

__global__ void __launch_bounds__(128, 2) gemm_pk(
    const float* __restrict__ pA,
    const float* __restrict__ pB0, const float* __restrict__ pB1,
    const float* __restrict__ pB2,
    const float* __restrict__ bi0, const float* __restrict__ bi1,
    const float* __restrict__ bi2,
    float* __restrict__ o0, float* __restrict__ o1, float* __restrict__ o2,
    int md0, int md1, int md2, float sc0, float sc1, float sc2,
    int rn0, int rn1, int rn2) {
  extern __shared__ __align__(16) char smem[];
  const int tid = threadIdx.x;
  const int w = tid >> 5, lane = tid & 31;
  const int r = lane >> 2, c = lane & 3;
  const int wm = w >> 1, wn = w & 1;
  const int z = blockIdx.z;
  const float* pB = (z == 0) ? pB0 : ((z == 1) ? pB1 : pB2);
  const float* bias = (z == 0) ? bi0 : ((z == 1) ? bi1 : bi2);
  float* out = (z == 0) ? o0 : ((z == 1) ? o1 : o2);
  const int mode = (z == 0) ? md0 : ((z == 1) ? md1 : md2);
  const float scale = (z == 0) ? sc0 : ((z == 1) ? sc1 : sc2);
  const int rnd = (z == 0) ? rn0 : ((z == 1) ? rn1 : rn2);

  const float* Ab = pA + (size_t)blockIdx.y * 8 * 16384;
  const float* Bb = pB + (size_t)blockIdx.x * 16 * 8192;
  const uint32_t sb = smem_u32(smem);

  float acc[4][8][4] = {};

  // One k32 stage: A 16KB (1024 segs), B 16KB (1024 segs); 128 threads.
  auto load_iter = [&](int it, int s) {
    uint32_t sa = sb + s * GSTG;
    const int it2 = it * 2;
#pragma unroll
    for (int i = 0; i < 8; i++) {
      int cid = tid + i * 128;                 // 0..1023
      int mt = cid >> 7, itk = (cid >> 6) & 1, k2 = cid & 63;
      CP_ASYNC16(sa + cid * 16,
                 Ab + (size_t)mt * 16384 + (it2 + itk) * 256 + k2 * 4);
    }
#pragma unroll
    for (int i = 0; i < 8; i++) {
      int cid = tid + i * 128;                 // 0..1023
      int nt = cid >> 6, itk = (cid >> 5) & 1, ln = cid & 31;
      CP_ASYNC16(sa + 16384 + cid * 16,
                 Bb + (size_t)nt * 8192 + (it2 + itk) * 128 + ln * 4);
    }
    CP_COMMIT();
  };

  load_iter(0, 0);
  load_iter(1, 1);

  for (int it = 0; it < 32; it++) {
    CP_WAIT(1);
    __syncthreads();
    const int nx = it + 2;
    if (nx < 32) load_iter(nx, nx % 3); else CP_COMMIT();
    const char* st = smem + (it % 3) * GSTG;
#pragma unroll
    for (int itk = 0; itk < 2; itk++) {
      uint4 bfr[8];
#pragma unroll
      for (int n = 0; n < 8; n++)
        bfr[n] = *(const uint4*)(st + 16384 +
                                 (((wn * 8 + n) * 64 + itk * 32) + lane) * 16);
#pragma unroll
      for (int ks = 0; ks < 2; ks++) {
        uint4 afr[4];
#pragma unroll
        for (int m = 0; m < 4; m++)
          afr[m] = *(const uint4*)(st +
                   (((wm * 4 + m) * 128 + itk * 64 + ks * 32) + lane) * 16);
#pragma unroll
        for (int n = 0; n < 8; n++) {
          unsigned b0 = ks ? bfr[n].z : bfr[n].x;
          unsigned b1 = ks ? bfr[n].w : bfr[n].y;
#pragma unroll
          for (int m = 0; m < 4; m++)
            mma8(acc[m][n], (const unsigned*)&afr[m], b0, b1);
        }
      }
    }
  }

  // epilogue
#pragma unroll
  for (int m = 0; m < 4; m++) {
    const int row0 = blockIdx.y * 128 + (wm * 4 + m) * 16 + r;
#pragma unroll
    for (int n = 0; n < 8; n++) {
      const int col = blockIdx.x * 128 + (wn * 8 + n) * 8 + 2 * c;
      const float b0 = bias[col], b1 = bias[col + 1];
#pragma unroll
      for (int hf = 0; hf < 2; hf++) {
        const int row = row0 + 8 * hf;
        float v0 = acc[m][n][2 * hf] + b0;
        float v1 = acc[m][n][2 * hf + 1] + b1;
        float q0 = (mode == 2) ? -v1 : v0;
        float q1 = (mode == 2) ? v0 : v1;
        if (rnd) {
          q0 = __uint_as_float(f2tf(q0 * scale));
          q1 = __uint_as_float(f2tf(q1 * scale));
        }
        float2 o = make_float2(q0, q1);
        if (mode == 0) {
          *(float2*)(out + (size_t)row * DM + col) = o;
        } else {
          int b_ = row >> 11, t = row & (TT - 1);
          int h = col >> 6, dh = col & (DH - 1);
          *(float2*)(out + ((size_t)(b_ * NH + h) * TT + t) * DH + dh) = o;
        }
      }
    }
  }
}

// ---------------------------------------------------------------------------
// Flash attention v3 (unchanged from R6/R7 — proven).
// ---------------------------------------------------------------------------
#define KVSTG 35840
#define PS_OFF 71680
#define ATTN_SMEM (2 * KVSTG + 34816)   // 106496

__global__ void __launch_bounds__(256, 2) attn3(
    const float* __restrict__ Q, const float* __restrict__ K,
    const float* __restrict__ V, float* __restrict__ pOut) {
  extern __shared__ __align__(16) char sm[];
  const uint32_t sb = smem_u32(sm);
  const int tid = threadIdx.x, w = tid >> 5, lane = tid & 31;
  const int r = lane >> 2, c = lane & 3;
  const int qb = gridDim.x - 1 - blockIdx.x;  // longest first
  const int bh = blockIdx.y;

  auto fill = [&](int jt, int s) {
    const float* Kg = K + ((size_t)bh * TT + jt * 64) * DH;
    const float* Vg = V + ((size_t)bh * TT + jt * 64) * DH;
    const uint32_t kb = sb + s * KVSTG;
    const uint32_t vb = kb + 17408;
#pragma unroll
    for (int i = 0; i < 4; i++) {
      int id = tid + i * 256;
      int row = id >> 4, sc = id & 15;
      CP_ASYNC16(kb + row * 272 + sc * 16, Kg + row * DH + sc * 4);
    }
#pragma unroll
    for (int i = 0; i < 4; i++) {
      int id = tid + i * 256;
      int row = id >> 4, sc = id & 15;
      CP_ASYNC16(vb + row * 288 + sc * 16, Vg + row * DH + sc * 4);
    }
    CP_COMMIT();
  };

  const unsigned* Qu =
      (const unsigned*)(Q + ((size_t)bh * TT + qb * 128 + 16 * w) * DH);
  unsigned qa[8][4];
#pragma unroll
  for (int kc = 0; kc < 8; kc++) {
    qa[kc][0] = Qu[r * DH + kc * 8 + c];
    qa[kc][1] = Qu[(r + 8) * DH + kc * 8 + c];
    qa[kc][2] = Qu[r * DH + kc * 8 + c + 4];
    qa[kc][3] = Qu[(r + 8) * DH + kc * 8 + c + 4];
  }

  float o[8][4] = {};
  float mrow[2] = {-1e30f, -1e30f}, lrow[2] = {0.f, 0.f};

  const int nkt = 2 * (qb + 1);
  fill(0, 0);

  for (int jt = 0; jt < nkt; jt++) {
    const int s = jt & 1;
    __syncthreads();
    if (jt + 1 < nkt) {
      fill(jt + 1, s ^ 1);
      CP_WAIT(1);
    } else {
      CP_WAIT(0);
    }
    __syncthreads();

    const char* kbuf = sm + s * KVSTG;
    const char* vbuf = kbuf + 17408;

    float sacc[8][4] = {};
#pragma unroll
    for (int kc = 0; kc < 8; kc++) {
#pragma unroll
      for (int ni = 0; ni < 8; ni++) {
        const unsigned* bp =
            (const unsigned*)(kbuf + (8 * ni + r) * 272 + (kc * 8 + c) * 4);
        mma8(sacc[ni], qa[kc], bp[0], bp[4]);
      }
    }

    if (jt >= 2 * qb) {
      const int qrow0 = qb * 128 + 16 * w + r;
#pragma unroll
      for (int ni = 0; ni < 8; ni++) {
        const int key0 = jt * 64 + 8 * ni + 2 * c;
#pragma unroll
        for (int reg = 0; reg < 4; reg++) {
          int key = key0 + (reg & 1);
          int qr = qrow0 + 8 * (reg >> 1);
          if (key > qr) sacc[ni][reg] = -1e30f;
        }
      }
    }

#pragma unroll
    for (int h = 0; h < 2; h++) {
      float mx = -1e30f;
#pragma unroll
      for (int ni = 0; ni < 8; ni++)
        mx = fmaxf(mx, fmaxf(sacc[ni][2 * h], sacc[ni][2 * h + 1]));
      mx = fmaxf(mx, __shfl_xor_sync(0xffffffffu, mx, 1));
      mx = fmaxf(mx, __shfl_xor_sync(0xffffffffu, mx, 2));
      float mnew = fmaxf(mrow[h], mx);
      float corr = exp2f(mrow[h] - mnew);
      mrow[h] = mnew;
      float rs = 0.f;
#pragma unroll
      for (int ni = 0; ni < 8; ni++) {
        sacc[ni][2 * h] = exp2f(sacc[ni][2 * h] - mnew);
        sacc[ni][2 * h + 1] = exp2f(sacc[ni][2 * h + 1] - mnew);
        rs += sacc[ni][2 * h] + sacc[ni][2 * h + 1];
      }
      rs += __shfl_xor_sync(0xffffffffu, rs, 1);
      rs += __shfl_xor_sync(0xffffffffu, rs, 2);
      lrow[h] = lrow[h] * corr + rs;
#pragma unroll
      for (int ni = 0; ni < 8; ni++) {
        o[ni][2 * h] *= corr;
        o[ni][2 * h + 1] *= corr;
      }
    }

    {
      const int prow = 16 * w + r;
#pragma unroll
      for (int ni = 0; ni < 8; ni++) {
        unsigned* p0 =
            (unsigned*)(sm + PS_OFF + prow * 272 + (8 * ni + 2 * c) * 4);
        unsigned* p1 =
            (unsigned*)(sm + PS_OFF + (prow + 8) * 272 + (8 * ni + 2 * c) * 4);
        p0[0] = f2tf(sacc[ni][0]);
        p0[1] = f2tf(sacc[ni][1]);
        p1[0] = f2tf(sacc[ni][2]);
        p1[1] = f2tf(sacc[ni][3]);
      }
    }
    __syncwarp();
#pragma unroll
    for (int kc = 0; kc < 8; kc++) {
      const unsigned* pp =
          (const unsigned*)(sm + PS_OFF + (16 * w + r) * 272 + (kc * 8 + c) * 4);
      unsigned pa[4];
      pa[0] = pp[0];
      pa[1] = pp[8 * 68];
      pa[2] = pp[4];
      pa[3] = pp[8 * 68 + 4];
#pragma unroll
      for (int ni = 0; ni < 8; ni++) {
        const unsigned* vp =
            (const unsigned*)(vbuf + (kc * 8 + c) * 288 + (8 * ni + r) * 4);
        mma8(o[ni], pa, vp[0], vp[4 * 72]);
      }
    }
  }

  const int b_ = bh >> 4, hh = bh & (NH - 1);
  const int mtile = b_ * 128 + qb * 8 + w;
#pragma unroll
  for (int h = 0; h < 2; h++) {
    const float inv = 1.0f / lrow[h];
#pragma unroll
    for (int ni = 0; ni < 8; ni++) {
      const int kt = hh * 8 + ni;
#pragma unroll
      for (int jp = 0; jp < 2; jp++) {
        int cc = 2 * c + jp;
        int cp = cc & 3, chi = cc >> 2;
        int jj = h + 2 * chi;
        size_t ad = ((size_t)mtile * 128 + kt) * 128 + (r * 4 + cp) * 4 + jj;
        pOut[ad] = __uint_as_float(f2tf(o[ni][2 * h + jp] * inv));
      }
    }
  }
}

extern "C" void kernel_launch(void* const* d_in, const int* in_sizes, int n_in,
                              void* d_out, int out_size) {
  const float* x  = (const float*)d_in[0];
  const float* Wq = (const float*)d_in[1];
  const float* bq = (const float*)d_in[2];
  const float* Wk = (const float*)d_in[3];
  const float* bk = (const float*)d_in[4];
  const float* Wv = (const float*)d_in[5];
  const float* bv = (const float*)d_in[6];
  const float* Wo = (const float*)d_in[7];
  const float* bo = (const float*)d_in[8];
  float* out = (float*)d_out;

  float *qp, *kp, *vp, *ap, *xp, *wp;
  cudaGetSymbolAddress((void**)&qp, g_q);
  cudaGetSymbolAddress((void**)&kp, g_k);
  cudaGetSymbolAddress((void**)&vp, g_v);
  cudaGetSymbolAddress((void**)&ap, g_attp);
  cudaGetSymbolAddress((void**)&xp, g_xp);
  cudaGetSymbolAddress((void**)&wp, g_wp);

  static int attr_set = 0;
  if (!attr_set) {
    cudaFuncSetAttribute(gemm_pk, cudaFuncAttributeMaxDynamicSharedMemorySize,
                         GEMM_SMEM);
    cudaFuncSetAttribute(attn3, cudaFuncAttributeMaxDynamicSharedMemorySize,
                         ATTN_SMEM);
    attr_set = 1;
  }

  const float QSCALE = 0.125f * 1.4426950408889634f;  // 1/sqrt(Dh) * log2(e)
  const size_t WSZ = (size_t)DM * DM;

  // 1) pack inputs into fragment layouts (tf32-rounded)
  pack_all<<<dim3(512, 1, 5), 256>>>(x, Wq, Wk, Wv, Wo, xp, wp);

  // 2) fused QKV projections; outputs rounded to tf32, Q pre-scaled
  gemm_pk<<<dim3(8, 32, 3), 128, GEMM_SMEM>>>(
      xp, wp, wp + WSZ, wp + 2 * WSZ, bq, bk, bv, qp, kp, vp,
      2, 2, 1, QSCALE, 1.f, 1.f, 1, 1, 1);

  // 3) attention -> packed-A fragments
  attn3<<<dim3(16, 32), 256, ATTN_SMEM>>>(qp, kp, vp, ap);

  // 4) output projection
  gemm_pk<<<dim3(8, 32, 1), 128, GEMM_SMEM>>>(
      ap, wp + 3 * WSZ, wp + 3 * WSZ, wp + 3 * WSZ, bo, bo, bo, out, out, out,
      0, 0, 0, 1.f, 1.f, 1.f, 0, 0, 0);
}

// round 9
// speedup vs baseline: 5.4319x; 1.3254x over previous
#include <cuda_runtime.h>
#include <cuda_fp16.h>
#include <cstdint>

#define BB 2
#define TT 2048
#define DM 1024
#define NH 16
#define DH 64
#define MM (BB * TT)   // 4096

// Scratch (device globals; no allocation allowed)
__device__ float g_q[BB * NH * TT * DH];       // [B,H,T,Dh], tf32, *0.125*log2e
__device__ float g_k[BB * NH * TT * DH];       // [B,H,T,Dh], tf32
__device__ float g_v[BB * NH * TT * DH];       // [B,H,T,Dh], tf32
__device__ uint32_t g_attp[MM * DM / 2];       // attn out, fp16 packed-A frags
__device__ uint32_t g_xp[MM * DM / 2];         // x fp16 packed-A frags
__device__ uint32_t g_wp[4 * DM * DM / 2];     // W's fp16 packed-B frags

// ---------------------------------------------------------------------------
// helpers
// ---------------------------------------------------------------------------
__device__ __forceinline__ uint32_t smem_u32(const void* p) {
  uint32_t a;
  asm("{ .reg .u64 t; cvta.to.shared.u64 t, %1; cvt.u32.u64 %0, t; }"
      : "=r"(a) : "l"(p));
  return a;
}

__device__ __forceinline__ unsigned f2tf(float f) {
  unsigned u;
  asm("cvt.rna.tf32.f32 %0, %1;" : "=r"(u) : "f"(f));
  return u;
}

__device__ __forceinline__ uint32_t h2u(float lo, float hi) {
  __half2 h = __floats2half2_rn(lo, hi);
  return *reinterpret_cast<uint32_t*>(&h);
}

// tf32 m16n8k8 (attention only)
__device__ __forceinline__ void mma8(float* c, const unsigned* a,
                                     unsigned b0, unsigned b1) {
  asm("mma.sync.aligned.m16n8k8.row.col.f32.tf32.tf32.f32 "
      "{%0,%1,%2,%3},{%4,%5,%6,%7},{%8,%9},{%0,%1,%2,%3};"
      : "+f"(c[0]), "+f"(c[1]), "+f"(c[2]), "+f"(c[3])
      : "r"(a[0]), "r"(a[1]), "r"(a[2]), "r"(a[3]), "r"(b0), "r"(b1));
}

// fp16 m16n8k16 (GEMMs)
__device__ __forceinline__ void mma16(float* c, const unsigned* a,
                                      unsigned b0, unsigned b1) {
  asm("mma.sync.aligned.m16n8k16.row.col.f32.f16.f16.f32 "
      "{%0,%1,%2,%3},{%4,%5,%6,%7},{%8,%9},{%0,%1,%2,%3};"
      : "+f"(c[0]), "+f"(c[1]), "+f"(c[2]), "+f"(c[3])
      : "r"(a[0]), "r"(a[1]), "r"(a[2]), "r"(a[3]), "r"(b0), "r"(b1));
}

#define CP_ASYNC16(dst, src) \
  asm volatile("cp.async.cg.shared.global [%0], [%1], 16;" :: "r"(dst), "l"(src))
#define CP_COMMIT() asm volatile("cp.async.commit_group;" ::: "memory")
#define CP_WAIT(n)  asm volatile("cp.async.wait_group %0;" :: "n"(n) : "memory")

// ---------------------------------------------------------------------------
// Packing into fp16 mma fragment order.
// A-chunk (m16 tile mt, k16 chunk kt): 128 words at (mt*64+kt)*128;
//   word [lane*4 + reg], lane=(g&7)*4+t, reg=(g>>3)+2*(q>>3), value
//   f16x2{A[row][2t(+8)], A[row][2t+1(+9)]}.
// B-chunk (n8 tile nt, k16 chunk kt): 64 words at (nt*64+kt)*64;
//   word [lane*2 + reg], lane=g*4+t (g=n&7), reg=q>>3.
// ---------------------------------------------------------------------------
__global__ void pack_all(const float* __restrict__ x,
                         const float* __restrict__ Wq,
                         const float* __restrict__ Wk,
                         const float* __restrict__ Wv,
                         const float* __restrict__ Wo,
                         uint32_t* __restrict__ pX,
                         uint32_t* __restrict__ pW) {
  const int z = blockIdx.z;
  const int idx0 = blockIdx.x * blockDim.x + threadIdx.x;
  const int stride = gridDim.x * blockDim.x;
  if (z == 0) {
    for (int idx = idx0; idx < MM * 256; idx += stride) {
      int m = idx >> 8, k4 = (idx & 255) * 4;
      float4 v = *(const float4*)(x + (size_t)m * DM + k4);
      int mt = m >> 4, g = m & 15;
      int kt = k4 >> 4, q = k4 & 15;
      int t0 = (q & 7) >> 1, reg = (g >> 3) + 2 * (q >> 3);
      uint32_t* d = pX + (size_t)(mt * 64 + kt) * 128 + reg;
      d[((g & 7) * 4 + t0) * 4] = h2u(v.x, v.y);
      d[((g & 7) * 4 + t0 + 1) * 4] = h2u(v.z, v.w);
    }
  } else {
    const float* W = (z == 1) ? Wq : ((z == 2) ? Wk : ((z == 3) ? Wv : Wo));
    uint32_t* dst = pW + (size_t)(z - 1) * (DM * DM / 2);
    for (int idx = idx0; idx < DM * 256; idx += stride) {
      int n = idx >> 8, k4 = (idx & 255) * 4;
      float4 v = *(const float4*)(W + (size_t)n * DM + k4);
      int nt = n >> 3, g = n & 7;
      int kt = k4 >> 4, q = k4 & 15;
      int t0 = (q & 7) >> 1, reg = q >> 3;
      uint32_t* d = dst + (size_t)(nt * 64 + kt) * 64 + reg;
      d[(g * 4 + t0) * 2] = h2u(v.x, v.y);
      d[(g * 4 + t0 + 1) * 2] = h2u(v.z, v.w);
    }
  }
}

// ---------------------------------------------------------------------------
// GEMM v5 (fp16 m16n8k16): out = A[M,1024] @ W[1024,1024]^T + bias
// Block 128x128, 8 warps (2m x 4n), warp tile 64x32.
// k-step 32, 4-stage cp.async (16KB/stage).
// Per k16 per warp: 4 LDS.128 (A) + 4 LDS.64 (B) -> 16 HMMA.16816.
// modes: 0 plain [M,DM]; 1 head-split [B,H,T,Dh]; 2 head-split+rotate_half.
// rnd: round output to tf32 after *scale (for attention consumption).
// ---------------------------------------------------------------------------
#define GSTG 16384
#define GEMM_SMEM (4 * GSTG)   // 65536

__global__ void __launch_bounds__(256, 2) gemm_fp16(
    const uint32_t* __restrict__ pA,
    const uint32_t* __restrict__ pB0, const uint32_t* __restrict__ pB1,
    const uint32_t* __restrict__ pB2,
    const float* __restrict__ bi0, const float* __restrict__ bi1,
    const float* __restrict__ bi2,
    float* __restrict__ o0, float* __restrict__ o1, float* __restrict__ o2,
    int md0, int md1, int md2, float sc0, float sc1, float sc2,
    int rn0, int rn1, int rn2) {
  extern __shared__ __align__(16) char smem[];
  const int tid = threadIdx.x;
  const int w = tid >> 5, lane = tid & 31;
  const int r = lane >> 2, c = lane & 3;
  const int wm = w >> 2, wn = w & 3;
  const int z = blockIdx.z;
  const uint32_t* pB = (z == 0) ? pB0 : ((z == 1) ? pB1 : pB2);
  const float* bias = (z == 0) ? bi0 : ((z == 1) ? bi1 : bi2);
  float* out = (z == 0) ? o0 : ((z == 1) ? o1 : o2);
  const int mode = (z == 0) ? md0 : ((z == 1) ? md1 : md2);
  const float scale = (z == 0) ? sc0 : ((z == 1) ? sc1 : sc2);
  const int rnd = (z == 0) ? rn0 : ((z == 1) ? rn1 : rn2);

  // block A: 8 m-tiles x 64 kt x 128 words; block B: 16 nt x 64 kt x 64 words
  const char* Ab = (const char*)(pA + ((size_t)blockIdx.y << 16));
  const char* Bb = (const char*)(pB + ((size_t)blockIdx.x << 16));
  const uint32_t sb = smem_u32(smem);

  float acc[4][4][4] = {};

  // One k32 stage: A 8KB (512 x 16B), B 8KB (512 x 16B).
  auto load_iter = [&](int it, int s) {
    uint32_t sa = sb + s * GSTG;
    const int it2 = it * 2;
#pragma unroll
    for (int i = 0; i < 2; i++) {
      int cid = tid + i * 256;                  // 0..511
      int mt = cid >> 6, ktl = (cid >> 5) & 1, off = cid & 31;
      CP_ASYNC16(sa + ((mt * 2 + ktl) * 32 + off) * 16,
                 Ab + ((size_t)(mt * 64 + it2 + ktl) * 32 + off) * 16);
    }
#pragma unroll
    for (int i = 0; i < 2; i++) {
      int cid = tid + i * 256;                  // 0..511
      int nt = cid >> 5, ktl = (cid >> 4) & 1, off = cid & 15;
      CP_ASYNC16(sa + 8192 + ((nt * 2 + ktl) * 16 + off) * 16,
                 Bb + ((size_t)(nt * 64 + it2 + ktl) * 16 + off) * 16);
    }
    CP_COMMIT();
  };

  load_iter(0, 0);
  load_iter(1, 1);
  load_iter(2, 2);

  for (int it = 0; it < 32; it++) {
    CP_WAIT(2);
    __syncthreads();
    const int nx = it + 3;
    if (nx < 32) load_iter(nx, nx & 3); else CP_COMMIT();
    const char* st = smem + (it & 3) * GSTG;
#pragma unroll
    for (int ktl = 0; ktl < 2; ktl++) {
      uint2 bfr[4];
#pragma unroll
      for (int n = 0; n < 4; n++)
        bfr[n] = *(const uint2*)(st + 8192 +
                                 (((wn * 4 + n) * 2 + ktl) * 32 + lane) * 8);
      uint4 afr[4];
#pragma unroll
      for (int m = 0; m < 4; m++)
        afr[m] = *(const uint4*)(st +
                                 (((wm * 4 + m) * 2 + ktl) * 32 + lane) * 16);
#pragma unroll
      for (int n = 0; n < 4; n++)
#pragma unroll
        for (int m = 0; m < 4; m++)
          mma16(acc[m][n], (const unsigned*)&afr[m], bfr[n].x, bfr[n].y);
    }
  }

  // epilogue
#pragma unroll
  for (int m = 0; m < 4; m++) {
    const int row0 = blockIdx.y * 128 + (wm * 4 + m) * 16 + r;
#pragma unroll
    for (int n = 0; n < 4; n++) {
      const int col = blockIdx.x * 128 + (wn * 4 + n) * 8 + 2 * c;
      const float b0 = bias[col], b1 = bias[col + 1];
#pragma unroll
      for (int hf = 0; hf < 2; hf++) {
        const int row = row0 + 8 * hf;
        float v0 = acc[m][n][2 * hf] + b0;
        float v1 = acc[m][n][2 * hf + 1] + b1;
        float q0 = (mode == 2) ? -v1 : v0;
        float q1 = (mode == 2) ? v0 : v1;
        if (rnd) {
          q0 = __uint_as_float(f2tf(q0 * scale));
          q1 = __uint_as_float(f2tf(q1 * scale));
        }
        float2 o = make_float2(q0, q1);
        if (mode == 0) {
          *(float2*)(out + (size_t)row * DM + col) = o;
        } else {
          int b_ = row >> 11, t = row & (TT - 1);
          int h = col >> 6, dh = col & (DH - 1);
          *(float2*)(out + ((size_t)(b_ * NH + h) * TT + t) * DH + dh) = o;
        }
      }
    }
  }
}

// ---------------------------------------------------------------------------
// Flash attention v3 (tf32 internals, proven) — epilogue now emits fp16
// packed-A fragments for the O-projection.
// ---------------------------------------------------------------------------
#define KVSTG 35840
#define PS_OFF 71680
#define ATTN_SMEM (2 * KVSTG + 34816)   // 106496

__global__ void __launch_bounds__(256, 2) attn3(
    const float* __restrict__ Q, const float* __restrict__ K,
    const float* __restrict__ V, uint32_t* __restrict__ pOut) {
  extern __shared__ __align__(16) char sm[];
  const uint32_t sb = smem_u32(sm);
  const int tid = threadIdx.x, w = tid >> 5, lane = tid & 31;
  const int r = lane >> 2, c = lane & 3;
  const int qb = gridDim.x - 1 - blockIdx.x;  // longest first
  const int bh = blockIdx.y;

  auto fill = [&](int jt, int s) {
    const float* Kg = K + ((size_t)bh * TT + jt * 64) * DH;
    const float* Vg = V + ((size_t)bh * TT + jt * 64) * DH;
    const uint32_t kb = sb + s * KVSTG;
    const uint32_t vb = kb + 17408;
#pragma unroll
    for (int i = 0; i < 4; i++) {
      int id = tid + i * 256;
      int row = id >> 4, sc = id & 15;
      CP_ASYNC16(kb + row * 272 + sc * 16, Kg + row * DH + sc * 4);
    }
#pragma unroll
    for (int i = 0; i < 4; i++) {
      int id = tid + i * 256;
      int row = id >> 4, sc = id & 15;
      CP_ASYNC16(vb + row * 288 + sc * 16, Vg + row * DH + sc * 4);
    }
    CP_COMMIT();
  };

  const unsigned* Qu =
      (const unsigned*)(Q + ((size_t)bh * TT + qb * 128 + 16 * w) * DH);
  unsigned qa[8][4];
#pragma unroll
  for (int kc = 0; kc < 8; kc++) {
    qa[kc][0] = Qu[r * DH + kc * 8 + c];
    qa[kc][1] = Qu[(r + 8) * DH + kc * 8 + c];
    qa[kc][2] = Qu[r * DH + kc * 8 + c + 4];
    qa[kc][3] = Qu[(r + 8) * DH + kc * 8 + c + 4];
  }

  float o[8][4] = {};
  float mrow[2] = {-1e30f, -1e30f}, lrow[2] = {0.f, 0.f};

  const int nkt = 2 * (qb + 1);
  fill(0, 0);

  for (int jt = 0; jt < nkt; jt++) {
    const int s = jt & 1;
    __syncthreads();
    if (jt + 1 < nkt) {
      fill(jt + 1, s ^ 1);
      CP_WAIT(1);
    } else {
      CP_WAIT(0);
    }
    __syncthreads();

    const char* kbuf = sm + s * KVSTG;
    const char* vbuf = kbuf + 17408;

    float sacc[8][4] = {};
#pragma unroll
    for (int kc = 0; kc < 8; kc++) {
#pragma unroll
      for (int ni = 0; ni < 8; ni++) {
        const unsigned* bp =
            (const unsigned*)(kbuf + (8 * ni + r) * 272 + (kc * 8 + c) * 4);
        mma8(sacc[ni], qa[kc], bp[0], bp[4]);
      }
    }

    if (jt >= 2 * qb) {
      const int qrow0 = qb * 128 + 16 * w + r;
#pragma unroll
      for (int ni = 0; ni < 8; ni++) {
        const int key0 = jt * 64 + 8 * ni + 2 * c;
#pragma unroll
        for (int reg = 0; reg < 4; reg++) {
          int key = key0 + (reg & 1);
          int qr = qrow0 + 8 * (reg >> 1);
          if (key > qr) sacc[ni][reg] = -1e30f;
        }
      }
    }

#pragma unroll
    for (int h = 0; h < 2; h++) {
      float mx = -1e30f;
#pragma unroll
      for (int ni = 0; ni < 8; ni++)
        mx = fmaxf(mx, fmaxf(sacc[ni][2 * h], sacc[ni][2 * h + 1]));
      mx = fmaxf(mx, __shfl_xor_sync(0xffffffffu, mx, 1));
      mx = fmaxf(mx, __shfl_xor_sync(0xffffffffu, mx, 2));
      float mnew = fmaxf(mrow[h], mx);
      float corr = exp2f(mrow[h] - mnew);
      mrow[h] = mnew;
      float rs = 0.f;
#pragma unroll
      for (int ni = 0; ni < 8; ni++) {
        sacc[ni][2 * h] = exp2f(sacc[ni][2 * h] - mnew);
        sacc[ni][2 * h + 1] = exp2f(sacc[ni][2 * h + 1] - mnew);
        rs += sacc[ni][2 * h] + sacc[ni][2 * h + 1];
      }
      rs += __shfl_xor_sync(0xffffffffu, rs, 1);
      rs += __shfl_xor_sync(0xffffffffu, rs, 2);
      lrow[h] = lrow[h] * corr + rs;
#pragma unroll
      for (int ni = 0; ni < 8; ni++) {
        o[ni][2 * h] *= corr;
        o[ni][2 * h + 1] *= corr;
      }
    }

    {
      const int prow = 16 * w + r;
#pragma unroll
      for (int ni = 0; ni < 8; ni++) {
        unsigned* p0 =
            (unsigned*)(sm + PS_OFF + prow * 272 + (8 * ni + 2 * c) * 4);
        unsigned* p1 =
            (unsigned*)(sm + PS_OFF + (prow + 8) * 272 + (8 * ni + 2 * c) * 4);
        p0[0] = f2tf(sacc[ni][0]);
        p0[1] = f2tf(sacc[ni][1]);
        p1[0] = f2tf(sacc[ni][2]);
        p1[1] = f2tf(sacc[ni][3]);
      }
    }
    __syncwarp();
#pragma unroll
    for (int kc = 0; kc < 8; kc++) {
      const unsigned* pp =
          (const unsigned*)(sm + PS_OFF + (16 * w + r) * 272 + (kc * 8 + c) * 4);
      unsigned pa[4];
      pa[0] = pp[0];
      pa[1] = pp[8 * 68];
      pa[2] = pp[4];
      pa[3] = pp[8 * 68 + 4];
#pragma unroll
      for (int ni = 0; ni < 8; ni++) {
        const unsigned* vp =
            (const unsigned*)(vbuf + (kc * 8 + c) * 288 + (8 * ni + r) * 4);
        mma8(o[ni], pa, vp[0], vp[4 * 72]);
      }
    }
  }

  // epilogue: normalize, convert to fp16 packed-A fragment layout.
  // (ni,h) -> word ((mtile*64 + kt)*32 + lane)*4 + j,
  //   kt = hh*4 + (ni>>1), j = h + 2*(ni&1).
  const int b_ = bh >> 4, hh = bh & (NH - 1);
  const int mtile = b_ * 128 + qb * 8 + w;
#pragma unroll
  for (int h = 0; h < 2; h++) {
    const float inv = 1.0f / lrow[h];
#pragma unroll
    for (int ni = 0; ni < 8; ni++) {
      const int kt = hh * 4 + (ni >> 1);
      const int j = h + 2 * (ni & 1);
      uint32_t wv = h2u(o[ni][2 * h] * inv, o[ni][2 * h + 1] * inv);
      pOut[(size_t)((mtile * 64 + kt) * 32 + lane) * 4 + j] = wv;
    }
  }
}

extern "C" void kernel_launch(void* const* d_in, const int* in_sizes, int n_in,
                              void* d_out, int out_size) {
  const float* x  = (const float*)d_in[0];
  const float* Wq = (const float*)d_in[1];
  const float* bq = (const float*)d_in[2];
  const float* Wk = (const float*)d_in[3];
  const float* bk = (const float*)d_in[4];
  const float* Wv = (const float*)d_in[5];
  const float* bv = (const float*)d_in[6];
  const float* Wo = (const float*)d_in[7];
  const float* bo = (const float*)d_in[8];
  float* out = (float*)d_out;

  float *qp, *kp, *vp;
  uint32_t *ap, *xp, *wp;
  cudaGetSymbolAddress((void**)&qp, g_q);
  cudaGetSymbolAddress((void**)&kp, g_k);
  cudaGetSymbolAddress((void**)&vp, g_v);
  cudaGetSymbolAddress((void**)&ap, g_attp);
  cudaGetSymbolAddress((void**)&xp, g_xp);
  cudaGetSymbolAddress((void**)&wp, g_wp);

  static int attr_set = 0;
  if (!attr_set) {
    cudaFuncSetAttribute(gemm_fp16, cudaFuncAttributeMaxDynamicSharedMemorySize,
                         GEMM_SMEM);
    cudaFuncSetAttribute(attn3, cudaFuncAttributeMaxDynamicSharedMemorySize,
                         ATTN_SMEM);
    attr_set = 1;
  }

  const float QSCALE = 0.125f * 1.4426950408889634f;  // 1/sqrt(Dh) * log2(e)
  const size_t WSZ = (size_t)DM * DM / 2;             // words per packed W

  // 1) pack inputs into fp16 fragment layouts
  pack_all<<<dim3(512, 1, 5), 256>>>(x, Wq, Wk, Wv, Wo, xp, wp);

  // 2) fused QKV projections; fp32 out rounded to tf32, Q pre-scaled
  gemm_fp16<<<dim3(8, 32, 3), 256, GEMM_SMEM>>>(
      xp, wp, wp + WSZ, wp + 2 * WSZ, bq, bk, bv, qp, kp, vp,
      2, 2, 1, QSCALE, 1.f, 1.f, 1, 1, 1);

  // 3) attention -> fp16 packed-A fragments
  attn3<<<dim3(16, 32), 256, ATTN_SMEM>>>(qp, kp, vp, ap);

  // 4) output projection
  gemm_fp16<<<dim3(8, 32, 1), 256, GEMM_SMEM>>>(
      ap, wp + 3 * WSZ, wp + 3 * WSZ, wp + 3 * WSZ, bo, bo, bo, out, out, out,
      0, 0, 0, 1.f, 1.f, 1.f, 0, 0, 0);
}

// round 10
// speedup vs baseline: 7.5679x; 1.3932x over previous
#include <cuda_runtime.h>
#include <cuda_fp16.h>
#include <cstdint>

#define BB 2
#define TT 2048
#define DM 1024
#define NH 16
#define DH 64
#define MM (BB * TT)   // 4096

// Scratch (device globals; no allocation allowed)
__device__ uint32_t g_q[BB * NH * TT * (DH / 2)];   // fp16 [B,H,T,Dh], *0.125*log2e
__device__ uint32_t g_k[BB * NH * TT * (DH / 2)];   // fp16 [B,H,T,Dh]
__device__ uint16_t g_vt[BB * NH * DH * TT];        // fp16 [B,H,Dh,T] (transposed)
__device__ uint32_t g_attp[MM * DM / 2];            // attn out, fp16 packed-A frags
__device__ uint32_t g_xp[MM * DM / 2];              // x fp16 packed-A frags
__device__ uint32_t g_wp[4 * DM * DM / 2];          // W's fp16 packed-B frags

// ---------------------------------------------------------------------------
// helpers
// ---------------------------------------------------------------------------
__device__ __forceinline__ uint32_t smem_u32(const void* p) {
  uint32_t a;
  asm("{ .reg .u64 t; cvta.to.shared.u64 t, %1; cvt.u32.u64 %0, t; }"
      : "=r"(a) : "l"(p));
  return a;
}

__device__ __forceinline__ uint32_t h2u(float lo, float hi) {
  __half2 h = __floats2half2_rn(lo, hi);
  return *reinterpret_cast<uint32_t*>(&h);
}

// fp16 m16n8k16
__device__ __forceinline__ void mma16(float* c, const unsigned* a,
                                      unsigned b0, unsigned b1) {
  asm("mma.sync.aligned.m16n8k16.row.col.f32.f16.f16.f32 "
      "{%0,%1,%2,%3},{%4,%5,%6,%7},{%8,%9},{%0,%1,%2,%3};"
      : "+f"(c[0]), "+f"(c[1]), "+f"(c[2]), "+f"(c[3])
      : "r"(a[0]), "r"(a[1]), "r"(a[2]), "r"(a[3]), "r"(b0), "r"(b1));
}

#define CP_ASYNC16(dst, src) \
  asm volatile("cp.async.cg.shared.global [%0], [%1], 16;" :: "r"(dst), "l"(src))
#define CP_COMMIT() asm volatile("cp.async.commit_group;" ::: "memory")
#define CP_WAIT(n)  asm volatile("cp.async.wait_group %0;" :: "n"(n) : "memory")

// ---------------------------------------------------------------------------
// Packing into fp16 mma fragment order (proven R9).
// ---------------------------------------------------------------------------
__global__ void pack_all(const float* __restrict__ x,
                         const float* __restrict__ Wq,
                         const float* __restrict__ Wk,
                         const float* __restrict__ Wv,
                         const float* __restrict__ Wo,
                         uint32_t* __restrict__ pX,
                         uint32_t* __restrict__ pW) {
  const int z = blockIdx.z;
  const int idx0 = blockIdx.x * blockDim.x + threadIdx.x;
  const int stride = gridDim.x * blockDim.x;
  if (z == 0) {
    for (int idx = idx0; idx < MM * 256; idx += stride) {
      int m = idx >> 8, k4 = (idx & 255) * 4;
      float4 v = *(const float4*)(x + (size_t)m * DM + k4);
      int mt = m >> 4, g = m & 15;
      int kt = k4 >> 4, q = k4 & 15;
      int t0 = (q & 7) >> 1, reg = (g >> 3) + 2 * (q >> 3);
      uint32_t* d = pX + (size_t)(mt * 64 + kt) * 128 + reg;
      d[((g & 7) * 4 + t0) * 4] = h2u(v.x, v.y);
      d[((g & 7) * 4 + t0 + 1) * 4] = h2u(v.z, v.w);
    }
  } else {
    const float* W = (z == 1) ? Wq : ((z == 2) ? Wk : ((z == 3) ? Wv : Wo));
    uint32_t* dst = pW + (size_t)(z - 1) * (DM * DM / 2);
    for (int idx = idx0; idx < DM * 256; idx += stride) {
      int n = idx >> 8, k4 = (idx & 255) * 4;
      float4 v = *(const float4*)(W + (size_t)n * DM + k4);
      int nt = n >> 3, g = n & 7;
      int kt = k4 >> 4, q = k4 & 15;
      int t0 = (q & 7) >> 1, reg = q >> 3;
      uint32_t* d = dst + (size_t)(nt * 64 + kt) * 64 + reg;
      d[(g * 4 + t0) * 2] = h2u(v.x, v.y);
      d[(g * 4 + t0 + 1) * 2] = h2u(v.z, v.w);
    }
  }
}

// ---------------------------------------------------------------------------
// GEMM (fp16 m16n8k16): out = A[M,1024] @ W[1024,1024]^T + bias
// Block 128x128, 8 warps (2m x 4n), k-step 32, 4-stage cp.async.
// modes: 0 plain fp32 [M,DM]; 2 head-split+rotate -> fp16 [B,H,T,Dh] (*scale);
//        3 head-split -> fp16 transposed [B,H,Dh,T].
// ---------------------------------------------------------------------------
#define GSTG 16384
#define GEMM_SMEM (4 * GSTG)   // 65536

__global__ void __launch_bounds__(256, 2) gemm_fp16(
    const uint32_t* __restrict__ pA,
    const uint32_t* __restrict__ pB0, const uint32_t* __restrict__ pB1,
    const uint32_t* __restrict__ pB2,
    const float* __restrict__ bi0, const float* __restrict__ bi1,
    const float* __restrict__ bi2,
    void* __restrict__ o0, void* __restrict__ o1, void* __restrict__ o2,
    int md0, int md1, int md2, float sc0, float sc1, float sc2) {
  extern __shared__ __align__(16) char smem[];
  const int tid = threadIdx.x;
  const int w = tid >> 5, lane = tid & 31;
  const int r = lane >> 2, c = lane & 3;
  const int wm = w >> 2, wn = w & 3;
  const int z = blockIdx.z;
  const uint32_t* pB = (z == 0) ? pB0 : ((z == 1) ? pB1 : pB2);
  const float* bias = (z == 0) ? bi0 : ((z == 1) ? bi1 : bi2);
  void* out = (z == 0) ? o0 : ((z == 1) ? o1 : o2);
  const int mode = (z == 0) ? md0 : ((z == 1) ? md1 : md2);
  const float scale = (z == 0) ? sc0 : ((z == 1) ? sc1 : sc2);

  const char* Ab = (const char*)(pA + ((size_t)blockIdx.y << 16));
  const char* Bb = (const char*)(pB + ((size_t)blockIdx.x << 16));
  const uint32_t sb = smem_u32(smem);

  float acc[4][4][4] = {};

  auto load_iter = [&](int it, int s) {
    uint32_t sa = sb + s * GSTG;
    const int it2 = it * 2;
#pragma unroll
    for (int i = 0; i < 2; i++) {
      int cid = tid + i * 256;
      int mt = cid >> 6, ktl = (cid >> 5) & 1, off = cid & 31;
      CP_ASYNC16(sa + ((mt * 2 + ktl) * 32 + off) * 16,
                 Ab + ((size_t)(mt * 64 + it2 + ktl) * 32 + off) * 16);
    }
#pragma unroll
    for (int i = 0; i < 2; i++) {
      int cid = tid + i * 256;
      int nt = cid >> 5, ktl = (cid >> 4) & 1, off = cid & 15;
      CP_ASYNC16(sa + 8192 + ((nt * 2 + ktl) * 16 + off) * 16,
                 Bb + ((size_t)(nt * 64 + it2 + ktl) * 16 + off) * 16);
    }
    CP_COMMIT();
  };

  load_iter(0, 0);
  load_iter(1, 1);
  load_iter(2, 2);

  for (int it = 0; it < 32; it++) {
    CP_WAIT(2);
    __syncthreads();
    const int nx = it + 3;
    if (nx < 32) load_iter(nx, nx & 3); else CP_COMMIT();
    const char* st = smem + (it & 3) * GSTG;
#pragma unroll
    for (int ktl = 0; ktl < 2; ktl++) {
      uint2 bfr[4];
#pragma unroll
      for (int n = 0; n < 4; n++)
        bfr[n] = *(const uint2*)(st + 8192 +
                                 (((wn * 4 + n) * 2 + ktl) * 32 + lane) * 8);
      uint4 afr[4];
#pragma unroll
      for (int m = 0; m < 4; m++)
        afr[m] = *(const uint4*)(st +
                                 (((wm * 4 + m) * 2 + ktl) * 32 + lane) * 16);
#pragma unroll
      for (int n = 0; n < 4; n++)
#pragma unroll
        for (int m = 0; m < 4; m++)
          mma16(acc[m][n], (const unsigned*)&afr[m], bfr[n].x, bfr[n].y);
    }
  }

  // epilogue
#pragma unroll
  for (int m = 0; m < 4; m++) {
    const int row0 = blockIdx.y * 128 + (wm * 4 + m) * 16 + r;
#pragma unroll
    for (int n = 0; n < 4; n++) {
      const int col = blockIdx.x * 128 + (wn * 4 + n) * 8 + 2 * c;
      const float b0 = bias[col], b1 = bias[col + 1];
#pragma unroll
      for (int hf = 0; hf < 2; hf++) {
        const int row = row0 + 8 * hf;
        float v0 = acc[m][n][2 * hf] + b0;
        float v1 = acc[m][n][2 * hf + 1] + b1;
        if (mode == 0) {
          *(float2*)((float*)out + (size_t)row * DM + col) =
              make_float2(v0, v1);
        } else {
          int b_ = row >> 11, t = row & (TT - 1);
          int h = col >> 6, dh = col & (DH - 1);
          if (mode == 2) {  // rotate_half + scale, fp16 [B,H,T,Dh]
            float q0 = -v1 * scale, q1 = v0 * scale;
            ((uint32_t*)out)[((size_t)(b_ * NH + h) * TT + t) * 32 + (dh >> 1)] =
                h2u(q0, q1);
          } else {  // mode 3: V^T fp16 [B,H,Dh,T]
            uint16_t* vt = (uint16_t*)out;
            __half h0 = __float2half_rn(v0), h1 = __float2half_rn(v1);
            vt[((size_t)(b_ * NH + h) * DH + dh) * TT + t] =
                *reinterpret_cast<uint16_t*>(&h0);
            vt[((size_t)(b_ * NH + h) * DH + dh + 1) * TT + t] =
                *reinterpret_cast<uint16_t*>(&h1);
          }
        }
      }
    }
  }
}

// ---------------------------------------------------------------------------
// Flash attention v4: fp16 m16n8k16 for QK^T and PV. 128-query tile,
// 64-key tiles, causal, base-2 online softmax (scale folded into Q).
// smem: stage s at s*18432: K 64x144B, V^T 64x144B; P at 36864 (128x144B).
// Output: fp16 packed-A fragments (R9 layout, proven).
// ---------------------------------------------------------------------------
#define STG 18432
#define PS_OFF 36864
#define ATTN_SMEM (2 * STG + 18432)   // 55296

__global__ void __launch_bounds__(256, 2) attn4(
    const uint32_t* __restrict__ Qw, const uint32_t* __restrict__ Kw,
    const uint16_t* __restrict__ Vt, uint32_t* __restrict__ pOut) {
  extern __shared__ __align__(16) char sm[];
  const uint32_t sb = smem_u32(sm);
  const int tid = threadIdx.x, w = tid >> 5, lane = tid & 31;
  const int r = lane >> 2, c = lane & 3;
  const int qb = gridDim.x - 1 - blockIdx.x;  // longest first
  const int bh = blockIdx.y;

  auto fill = [&](int jt, int s) {
    const uint32_t* Kg = Kw + ((size_t)(bh * TT + jt * 64)) * 32;
    const uint16_t* Vg = Vt + (size_t)bh * DH * TT + jt * 64;
    const uint32_t kb = sb + s * STG;
    const uint32_t vb = kb + 9216;
#pragma unroll
    for (int i = 0; i < 2; i++) {
      int id = tid + i * 256;           // 0..511
      int row = id >> 3, sc = id & 7;   // 64 rows x 8 segs
      CP_ASYNC16(kb + row * 144 + sc * 16, Kg + row * 32 + sc * 4);
    }
#pragma unroll
    for (int i = 0; i < 2; i++) {
      int id = tid + i * 256;
      int row = id >> 3, sc = id & 7;   // 64 dh-rows x 8 segs
      CP_ASYNC16(vb + row * 144 + sc * 16, Vg + (size_t)row * TT + sc * 8);
    }
    CP_COMMIT();
  };

  // Q A-fragments (fp16, pre-scaled): 4 k16 chunks x 4 regs
  const uint32_t* Qu = Qw + ((size_t)bh * TT + qb * 128 + 16 * w) * 32;
  unsigned qa[4][4];
#pragma unroll
  for (int kc = 0; kc < 4; kc++) {
    qa[kc][0] = Qu[r * 32 + 8 * kc + c];
    qa[kc][1] = Qu[(r + 8) * 32 + 8 * kc + c];
    qa[kc][2] = Qu[r * 32 + 8 * kc + c + 4];
    qa[kc][3] = Qu[(r + 8) * 32 + 8 * kc + c + 4];
  }

  float o[8][4] = {};
  float mrow[2] = {-1e30f, -1e30f}, lrow[2] = {0.f, 0.f};

  const int nkt = 2 * (qb + 1);
  fill(0, 0);

  for (int jt = 0; jt < nkt; jt++) {
    const int s = jt & 1;
    __syncthreads();
    if (jt + 1 < nkt) {
      fill(jt + 1, s ^ 1);
      CP_WAIT(1);
    } else {
      CP_WAIT(0);
    }
    __syncthreads();

    const char* kbuf = sm + s * STG;
    const char* vbuf = kbuf + 9216;

    // S = Q @ K^T (log2 domain): 4 kc x 8 ni mma16
    float sacc[8][4] = {};
#pragma unroll
    for (int kc = 0; kc < 4; kc++) {
#pragma unroll
      for (int ni = 0; ni < 8; ni++) {
        const uint32_t* bp =
            (const uint32_t*)(kbuf + (8 * ni + r) * 144 + (8 * kc + c) * 4);
        mma16(sacc[ni], qa[kc], bp[0], bp[4]);
      }
    }

    if (jt >= 2 * qb) {  // diagonal tiles: causal mask
      const int qrow0 = qb * 128 + 16 * w + r;
#pragma unroll
      for (int ni = 0; ni < 8; ni++) {
        const int key0 = jt * 64 + 8 * ni + 2 * c;
#pragma unroll
        for (int reg = 0; reg < 4; reg++) {
          int key = key0 + (reg & 1);
          int qr = qrow0 + 8 * (reg >> 1);
          if (key > qr) sacc[ni][reg] = -1e30f;
        }
      }
    }

    // online softmax (base-2)
#pragma unroll
    for (int h = 0; h < 2; h++) {
      float mx = -1e30f;
#pragma unroll
      for (int ni = 0; ni < 8; ni++)
        mx = fmaxf(mx, fmaxf(sacc[ni][2 * h], sacc[ni][2 * h + 1]));
      mx = fmaxf(mx, __shfl_xor_sync(0xffffffffu, mx, 1));
      mx = fmaxf(mx, __shfl_xor_sync(0xffffffffu, mx, 2));
      float mnew = fmaxf(mrow[h], mx);
      float corr = exp2f(mrow[h] - mnew);
      mrow[h] = mnew;
      float rs = 0.f;
#pragma unroll
      for (int ni = 0; ni < 8; ni++) {
        sacc[ni][2 * h] = exp2f(sacc[ni][2 * h] - mnew);
        sacc[ni][2 * h + 1] = exp2f(sacc[ni][2 * h + 1] - mnew);
        rs += sacc[ni][2 * h] + sacc[ni][2 * h + 1];
      }
      rs += __shfl_xor_sync(0xffffffffu, rs, 1);
      rs += __shfl_xor_sync(0xffffffffu, rs, 2);
      lrow[h] = lrow[h] * corr + rs;
#pragma unroll
      for (int ni = 0; ni < 8; ni++) {
        o[ni][2 * h] *= corr;
        o[ni][2 * h + 1] *= corr;
      }
    }

    // P -> smem fp16 (adjacent-column pairs pack into one u32)
    {
      const int prow = 16 * w + r;
#pragma unroll
      for (int ni = 0; ni < 8; ni++) {
        *(uint32_t*)(sm + PS_OFF + prow * 144 + (4 * ni + c) * 4) =
            h2u(sacc[ni][0], sacc[ni][1]);
        *(uint32_t*)(sm + PS_OFF + (prow + 8) * 144 + (4 * ni + c) * 4) =
            h2u(sacc[ni][2], sacc[ni][3]);
      }
    }
    __syncwarp();

    // O += P @ V : 4 kc x 8 ni mma16 with V^T B-fragments
#pragma unroll
    for (int kc = 0; kc < 4; kc++) {
      unsigned pa[4];
      pa[0] = *(const uint32_t*)(sm + PS_OFF + (16 * w + r) * 144 +
                                 (8 * kc + c) * 4);
      pa[1] = *(const uint32_t*)(sm + PS_OFF + (16 * w + r + 8) * 144 +
                                 (8 * kc + c) * 4);
      pa[2] = *(const uint32_t*)(sm + PS_OFF + (16 * w + r) * 144 +
                                 (8 * kc + c + 4) * 4);
      pa[3] = *(const uint32_t*)(sm + PS_OFF + (16 * w + r + 8) * 144 +
                                 (8 * kc + c + 4) * 4);
#pragma unroll
      for (int ni = 0; ni < 8; ni++) {
        const uint32_t* vp =
            (const uint32_t*)(vbuf + (8 * ni + r) * 144 + (8 * kc + c) * 4);
        mma16(o[ni], pa, vp[0], vp[4]);
      }
    }
  }

  // epilogue: normalize, fp16 packed-A fragment layout (R9, proven)
  const int b_ = bh >> 4, hh = bh & (NH - 1);
  const int mtile = b_ * 128 + qb * 8 + w;
#pragma unroll
  for (int h = 0; h < 2; h++) {
    const float inv = 1.0f / lrow[h];
#pragma unroll
    for (int ni = 0; ni < 8; ni++) {
      const int kt = hh * 4 + (ni >> 1);
      const int j = h + 2 * (ni & 1);
      uint32_t wv = h2u(o[ni][2 * h] * inv, o[ni][2 * h + 1] * inv);
      pOut[(size_t)((mtile * 64 + kt) * 32 + lane) * 4 + j] = wv;
    }
  }
}

extern "C" void kernel_launch(void* const* d_in, const int* in_sizes, int n_in,
                              void* d_out, int out_size) {
  const float* x  = (const float*)d_in[0];
  const float* Wq = (const float*)d_in[1];
  const float* bq = (const float*)d_in[2];
  const float* Wk = (const float*)d_in[3];
  const float* bk = (const float*)d_in[4];
  const float* Wv = (const float*)d_in[5];
  const float* bv = (const float*)d_in[6];
  const float* Wo = (const float*)d_in[7];
  const float* bo = (const float*)d_in[8];
  float* out = (float*)d_out;

  uint32_t *qp, *kp, *ap, *xp, *wp;
  uint16_t *vtp;
  cudaGetSymbolAddress((void**)&qp, g_q);
  cudaGetSymbolAddress((void**)&kp, g_k);
  cudaGetSymbolAddress((void**)&vtp, g_vt);
  cudaGetSymbolAddress((void**)&ap, g_attp);
  cudaGetSymbolAddress((void**)&xp, g_xp);
  cudaGetSymbolAddress((void**)&wp, g_wp);

  static int attr_set = 0;
  if (!attr_set) {
    cudaFuncSetAttribute(gemm_fp16, cudaFuncAttributeMaxDynamicSharedMemorySize,
                         GEMM_SMEM);
    cudaFuncSetAttribute(attn4, cudaFuncAttributeMaxDynamicSharedMemorySize,
                         ATTN_SMEM);
    attr_set = 1;
  }

  const float QSCALE = 0.125f * 1.4426950408889634f;  // 1/sqrt(Dh) * log2(e)
  const size_t WSZ = (size_t)DM * DM / 2;             // words per packed W

  // 1) pack inputs into fp16 fragment layouts
  pack_all<<<dim3(512, 1, 5), 256>>>(x, Wq, Wk, Wv, Wo, xp, wp);

  // 2) fused QKV: Q,K -> fp16 rot (+Q scale); V -> fp16 transposed
  gemm_fp16<<<dim3(8, 32, 3), 256, GEMM_SMEM>>>(
      xp, wp, wp + WSZ, wp + 2 * WSZ, bq, bk, bv, qp, kp, vtp,
      2, 2, 3, QSCALE, 1.f, 1.f);

  // 3) attention (all-fp16 mma) -> fp16 packed-A fragments
  attn4<<<dim3(16, 32), 256, ATTN_SMEM>>>(qp, kp, vtp, ap);

  // 4) output projection (fp32 out)
  gemm_fp16<<<dim3(8, 32, 1), 256, GEMM_SMEM>>>(
      ap, wp + 3 * WSZ, wp + 3 * WSZ, wp + 3 * WSZ, bo, bo, bo, out, out, out,
      0, 0, 0, 1.f, 1.f, 1.f);
}

// round 11
// speedup vs baseline: 7.8544x; 1.0379x over previous
#include <cuda_runtime.h>
#include <cuda_fp16.h>
#include <cstdint>

#define BB 2
#define TT 2048
#define DM 1024
#define NH 16
#define DH 64
#define MM (BB * TT)   // 4096

// Scratch (device globals; no allocation allowed)
__device__ uint32_t g_q[BB * NH * TT * (DH / 2)];   // fp16 [B,H,T,Dh], *0.125*log2e
__device__ uint32_t g_k[BB * NH * TT * (DH / 2)];   // fp16 [B,H,T,Dh]
__device__ uint16_t g_vt[BB * NH * DH * TT];        // fp16 [B,H,Dh,T] (transposed)
__device__ uint32_t g_attp[MM * DM / 2];            // attn out, fp16 packed-A frags
__device__ uint32_t g_xp[MM * DM / 2];              // x fp16 packed-A frags
__device__ uint32_t g_wp[4 * DM * DM / 2];          // W's fp16 packed-B frags

// ---------------------------------------------------------------------------
// helpers
// ---------------------------------------------------------------------------
__device__ __forceinline__ uint32_t smem_u32(const void* p) {
  uint32_t a;
  asm("{ .reg .u64 t; cvta.to.shared.u64 t, %1; cvt.u32.u64 %0, t; }"
      : "=r"(a) : "l"(p));
  return a;
}

__device__ __forceinline__ uint32_t h2u(float lo, float hi) {
  __half2 h = __floats2half2_rn(lo, hi);
  return *reinterpret_cast<uint32_t*>(&h);
}

// fp16 m16n8k16
__device__ __forceinline__ void mma16(float* c, const unsigned* a,
                                      unsigned b0, unsigned b1) {
  asm("mma.sync.aligned.m16n8k16.row.col.f32.f16.f16.f32 "
      "{%0,%1,%2,%3},{%4,%5,%6,%7},{%8,%9},{%0,%1,%2,%3};"
      : "+f"(c[0]), "+f"(c[1]), "+f"(c[2]), "+f"(c[3])
      : "r"(a[0]), "r"(a[1]), "r"(a[2]), "r"(a[3]), "r"(b0), "r"(b1));
}

#define CP_ASYNC16(dst, src) \
  asm volatile("cp.async.cg.shared.global [%0], [%1], 16;" :: "r"(dst), "l"(src))
#define CP_COMMIT() asm volatile("cp.async.commit_group;" ::: "memory")
#define CP_WAIT(n)  asm volatile("cp.async.wait_group %0;" :: "n"(n) : "memory")

// ---------------------------------------------------------------------------
// Packing into fp16 mma fragment order — coalesced version.
// A: each thread gathers one lane's uint4 (4x float2 loads, 1x 16B store).
// B: each thread gathers one lane's uint2 (2x float2 loads, 1x 8B store).
// Mapping identical to R9/R10 (proven).
// ---------------------------------------------------------------------------
__global__ void pack_all(const float* __restrict__ x,
                         const float* __restrict__ Wq,
                         const float* __restrict__ Wk,
                         const float* __restrict__ Wv,
                         const float* __restrict__ Wo,
                         uint32_t* __restrict__ pX,
                         uint32_t* __restrict__ pW) {
  const int z = blockIdx.z;
  const int idx0 = blockIdx.x * blockDim.x + threadIdx.x;
  const int stride = gridDim.x * blockDim.x;
  if (z == 0) {
    // (mt, kt, lane): 256 * 64 * 32
    for (int i = idx0; i < (MM / 16) * 64 * 32; i += stride) {
      int lane = i & 31, kt = (i >> 5) & 63, mt = i >> 11;
      int g7 = lane >> 2, t0 = lane & 3;
      const float* r0 = x + (size_t)(mt * 16 + g7) * DM + kt * 16 + 2 * t0;
      const float* r1 = r0 + 8 * DM;
      float2 a0 = *(const float2*)(r0);
      float2 a1 = *(const float2*)(r1);
      float2 a2 = *(const float2*)(r0 + 8);
      float2 a3 = *(const float2*)(r1 + 8);
      uint4 o = make_uint4(h2u(a0.x, a0.y), h2u(a1.x, a1.y),
                           h2u(a2.x, a2.y), h2u(a3.x, a3.y));
      *(uint4*)(pX + (size_t)((mt * 64 + kt) * 32 + lane) * 4) = o;
    }
  } else {
    const float* W = (z == 1) ? Wq : ((z == 2) ? Wk : ((z == 3) ? Wv : Wo));
    uint32_t* dst = pW + (size_t)(z - 1) * (DM * DM / 2);
    // (nt, kt, lane): 128 * 64 * 32
    for (int i = idx0; i < (DM / 8) * 64 * 32; i += stride) {
      int lane = i & 31, kt = (i >> 5) & 63, nt = i >> 11;
      int g = lane >> 2, t0 = lane & 3;
      const float* rw = W + (size_t)(nt * 8 + g) * DM + kt * 16 + 2 * t0;
      float2 b0 = *(const float2*)(rw);
      float2 b1 = *(const float2*)(rw + 8);
      uint2 o = make_uint2(h2u(b0.x, b0.y), h2u(b1.x, b1.y));
      *(uint2*)(dst + (size_t)((nt * 64 + kt) * 64 + lane * 2)) = o;
    }
  }
}

// ---------------------------------------------------------------------------
// GEMM (fp16 m16n8k16): out = A[M,1024] @ W[1024,1024]^T + bias
// Block 128x128, 8 warps (2m x 4n), k-step 32, 4-stage cp.async. (proven R10)
// modes: 0 plain fp32 [M,DM]; 2 head-split+rotate -> fp16 [B,H,T,Dh] (*scale);
//        3 head-split -> fp16 transposed [B,H,Dh,T].
// ---------------------------------------------------------------------------
#define GSTG 16384
#define GEMM_SMEM (4 * GSTG)   // 65536

__global__ void __launch_bounds__(256, 2) gemm_fp16(
    const uint32_t* __restrict__ pA,
    const uint32_t* __restrict__ pB0, const uint32_t* __restrict__ pB1,
    const uint32_t* __restrict__ pB2,
    const float* __restrict__ bi0, const float* __restrict__ bi1,
    const float* __restrict__ bi2,
    void* __restrict__ o0, void* __restrict__ o1, void* __restrict__ o2,
    int md0, int md1, int md2, float sc0, float sc1, float sc2) {
  extern __shared__ __align__(16) char smem[];
  const int tid = threadIdx.x;
  const int w = tid >> 5, lane = tid & 31;
  const int r = lane >> 2, c = lane & 3;
  const int wm = w >> 2, wn = w & 3;
  const int z = blockIdx.z;
  const uint32_t* pB = (z == 0) ? pB0 : ((z == 1) ? pB1 : pB2);
  const float* bias = (z == 0) ? bi0 : ((z == 1) ? bi1 : bi2);
  void* out = (z == 0) ? o0 : ((z == 1) ? o1 : o2);
  const int mode = (z == 0) ? md0 : ((z == 1) ? md1 : md2);
  const float scale = (z == 0) ? sc0 : ((z == 1) ? sc1 : sc2);

  const char* Ab = (const char*)(pA + ((size_t)blockIdx.y << 16));
  const char* Bb = (const char*)(pB + ((size_t)blockIdx.x << 16));
  const uint32_t sb = smem_u32(smem);

  float acc[4][4][4] = {};

  auto load_iter = [&](int it, int s) {
    uint32_t sa = sb + s * GSTG;
    const int it2 = it * 2;
#pragma unroll
    for (int i = 0; i < 2; i++) {
      int cid = tid + i * 256;
      int mt = cid >> 6, ktl = (cid >> 5) & 1, off = cid & 31;
      CP_ASYNC16(sa + ((mt * 2 + ktl) * 32 + off) * 16,
                 Ab + ((size_t)(mt * 64 + it2 + ktl) * 32 + off) * 16);
    }
#pragma unroll
    for (int i = 0; i < 2; i++) {
      int cid = tid + i * 256;
      int nt = cid >> 5, ktl = (cid >> 4) & 1, off = cid & 15;
      CP_ASYNC16(sa + 8192 + ((nt * 2 + ktl) * 16 + off) * 16,
                 Bb + ((size_t)(nt * 64 + it2 + ktl) * 16 + off) * 16);
    }
    CP_COMMIT();
  };

  load_iter(0, 0);
  load_iter(1, 1);
  load_iter(2, 2);

  for (int it = 0; it < 32; it++) {
    CP_WAIT(2);
    __syncthreads();
    const int nx = it + 3;
    if (nx < 32) load_iter(nx, nx & 3); else CP_COMMIT();
    const char* st = smem + (it & 3) * GSTG;
#pragma unroll
    for (int ktl = 0; ktl < 2; ktl++) {
      uint2 bfr[4];
#pragma unroll
      for (int n = 0; n < 4; n++)
        bfr[n] = *(const uint2*)(st + 8192 +
                                 (((wn * 4 + n) * 2 + ktl) * 32 + lane) * 8);
      uint4 afr[4];
#pragma unroll
      for (int m = 0; m < 4; m++)
        afr[m] = *(const uint4*)(st +
                                 (((wm * 4 + m) * 2 + ktl) * 32 + lane) * 16);
#pragma unroll
      for (int n = 0; n < 4; n++)
#pragma unroll
        for (int m = 0; m < 4; m++)
          mma16(acc[m][n], (const unsigned*)&afr[m], bfr[n].x, bfr[n].y);
    }
  }

  // epilogue
#pragma unroll
  for (int m = 0; m < 4; m++) {
    const int row0 = blockIdx.y * 128 + (wm * 4 + m) * 16 + r;
#pragma unroll
    for (int n = 0; n < 4; n++) {
      const int col = blockIdx.x * 128 + (wn * 4 + n) * 8 + 2 * c;
      const float b0 = bias[col], b1 = bias[col + 1];
#pragma unroll
      for (int hf = 0; hf < 2; hf++) {
        const int row = row0 + 8 * hf;
        float v0 = acc[m][n][2 * hf] + b0;
        float v1 = acc[m][n][2 * hf + 1] + b1;
        if (mode == 0) {
          *(float2*)((float*)out + (size_t)row * DM + col) =
              make_float2(v0, v1);
        } else {
          int b_ = row >> 11, t = row & (TT - 1);
          int h = col >> 6, dh = col & (DH - 1);
          if (mode == 2) {  // rotate_half + scale, fp16 [B,H,T,Dh]
            float q0 = -v1 * scale, q1 = v0 * scale;
            ((uint32_t*)out)[((size_t)(b_ * NH + h) * TT + t) * 32 + (dh >> 1)] =
                h2u(q0, q1);
          } else {  // mode 3: V^T fp16 [B,H,Dh,T]
            uint16_t* vt = (uint16_t*)out;
            __half h0 = __float2half_rn(v0), h1 = __float2half_rn(v1);
            vt[((size_t)(b_ * NH + h) * DH + dh) * TT + t] =
                *reinterpret_cast<uint16_t*>(&h0);
            vt[((size_t)(b_ * NH + h) * DH + dh + 1) * TT + t] =
                *reinterpret_cast<uint16_t*>(&h1);
          }
        }
      }
    }
  }
}

// ---------------------------------------------------------------------------
// Flash attention v5: fp16 mma, P kept entirely in registers — the QK
// C-fragment IS the PV A-fragment (no smem roundtrip, no syncwarp).
// 128-query tile, 64-key tiles, causal, base-2 online softmax.
// smem: stage s at s*18432: K 64x144B, V^T 64x144B. Double-buffered.
// Output: fp16 packed-A fragments, vectorized uint4 stores.
// ---------------------------------------------------------------------------
#define STG 18432
#define ATTN_SMEM (2 * STG)   // 36864

__global__ void __launch_bounds__(256, 2) attn5(
    const uint32_t* __restrict__ Qw, const uint32_t* __restrict__ Kw,
    const uint16_t* __restrict__ Vt, uint32_t* __restrict__ pOut) {
  extern __shared__ __align__(16) char sm[];
  const uint32_t sb = smem_u32(sm);
  const int tid = threadIdx.x, w = tid >> 5, lane = tid & 31;
  const int r = lane >> 2, c = lane & 3;
  const int qb = gridDim.x - 1 - blockIdx.x;  // longest first
  const int bh = blockIdx.y;

  auto fill = [&](int jt, int s) {
    const uint32_t* Kg = Kw + ((size_t)(bh * TT + jt * 64)) * 32;
    const uint16_t* Vg = Vt + (size_t)bh * DH * TT + jt * 64;
    const uint32_t kb = sb + s * STG;
    const uint32_t vb = kb + 9216;
#pragma unroll
    for (int i = 0; i < 2; i++) {
      int id = tid + i * 256;           // 0..511
      int row = id >> 3, sc = id & 7;   // 64 rows x 8 segs
      CP_ASYNC16(kb + row * 144 + sc * 16, Kg + row * 32 + sc * 4);
    }
#pragma unroll
    for (int i = 0; i < 2; i++) {
      int id = tid + i * 256;
      int row = id >> 3, sc = id & 7;   // 64 dh-rows x 8 segs
      CP_ASYNC16(vb + row * 144 + sc * 16, Vg + (size_t)row * TT + sc * 8);
    }
    CP_COMMIT();
  };

  // Q A-fragments (fp16, pre-scaled): 4 k16 chunks x 4 regs
  const uint32_t* Qu = Qw + ((size_t)bh * TT + qb * 128 + 16 * w) * 32;
  unsigned qa[4][4];
#pragma unroll
  for (int kc = 0; kc < 4; kc++) {
    qa[kc][0] = Qu[r * 32 + 8 * kc + c];
    qa[kc][1] = Qu[(r + 8) * 32 + 8 * kc + c];
    qa[kc][2] = Qu[r * 32 + 8 * kc + c + 4];
    qa[kc][3] = Qu[(r + 8) * 32 + 8 * kc + c + 4];
  }

  float o[8][4] = {};
  float mrow[2] = {-1e30f, -1e30f}, lrow[2] = {0.f, 0.f};

  const int nkt = 2 * (qb + 1);
  fill(0, 0);

  for (int jt = 0; jt < nkt; jt++) {
    const int s = jt & 1;
    __syncthreads();
    if (jt + 1 < nkt) {
      fill(jt + 1, s ^ 1);
      CP_WAIT(1);
    } else {
      CP_WAIT(0);
    }
    __syncthreads();

    const char* kbuf = sm + s * STG;
    const char* vbuf = kbuf + 9216;

    // S = Q @ K^T (log2 domain): 4 kc x 8 ni mma16
    float sacc[8][4] = {};
#pragma unroll
    for (int kc = 0; kc < 4; kc++) {
#pragma unroll
      for (int ni = 0; ni < 8; ni++) {
        const uint32_t* bp =
            (const uint32_t*)(kbuf + (8 * ni + r) * 144 + (8 * kc + c) * 4);
        mma16(sacc[ni], qa[kc], bp[0], bp[4]);
      }
    }

    if (jt >= 2 * qb) {  // diagonal tiles: causal mask
      const int qrow0 = qb * 128 + 16 * w + r;
#pragma unroll
      for (int ni = 0; ni < 8; ni++) {
        const int key0 = jt * 64 + 8 * ni + 2 * c;
#pragma unroll
        for (int reg = 0; reg < 4; reg++) {
          int key = key0 + (reg & 1);
          int qr = qrow0 + 8 * (reg >> 1);
          if (key > qr) sacc[ni][reg] = -1e30f;
        }
      }
    }

    // online softmax (base-2)
#pragma unroll
    for (int h = 0; h < 2; h++) {
      float mx = -1e30f;
#pragma unroll
      for (int ni = 0; ni < 8; ni++)
        mx = fmaxf(mx, fmaxf(sacc[ni][2 * h], sacc[ni][2 * h + 1]));
      mx = fmaxf(mx, __shfl_xor_sync(0xffffffffu, mx, 1));
      mx = fmaxf(mx, __shfl_xor_sync(0xffffffffu, mx, 2));
      float mnew = fmaxf(mrow[h], mx);
      float corr = exp2f(mrow[h] - mnew);
      mrow[h] = mnew;
      float rs = 0.f;
#pragma unroll
      for (int ni = 0; ni < 8; ni++) {
        sacc[ni][2 * h] = exp2f(sacc[ni][2 * h] - mnew);
        sacc[ni][2 * h + 1] = exp2f(sacc[ni][2 * h + 1] - mnew);
        rs += sacc[ni][2 * h] + sacc[ni][2 * h + 1];
      }
      rs += __shfl_xor_sync(0xffffffffu, rs, 1);
      rs += __shfl_xor_sync(0xffffffffu, rs, 2);
      lrow[h] = lrow[h] * corr + rs;
#pragma unroll
      for (int ni = 0; ni < 8; ni++) {
        o[ni][2 * h] *= corr;
        o[ni][2 * h + 1] *= corr;
      }
    }

    // O += P @ V : P A-fragments built directly from sacc registers
    // (QK C-frag layout == PV A-frag layout)
#pragma unroll
    for (int kc = 0; kc < 4; kc++) {
      unsigned pa[4];
      pa[0] = h2u(sacc[2 * kc][0], sacc[2 * kc][1]);
      pa[1] = h2u(sacc[2 * kc][2], sacc[2 * kc][3]);
      pa[2] = h2u(sacc[2 * kc + 1][0], sacc[2 * kc + 1][1]);
      pa[3] = h2u(sacc[2 * kc + 1][2], sacc[2 * kc + 1][3]);
#pragma unroll
      for (int ni = 0; ni < 8; ni++) {
        const uint32_t* vp =
            (const uint32_t*)(vbuf + (8 * ni + r) * 144 + (8 * kc + c) * 4);
        mma16(o[ni], pa, vp[0], vp[4]);
      }
    }
  }

  // epilogue: normalize, fp16 packed-A fragments, uint4 stores
  const int b_ = bh >> 4, hh = bh & (NH - 1);
  const int mtile = b_ * 128 + qb * 8 + w;
  const float inv0 = 1.0f / lrow[0], inv1 = 1.0f / lrow[1];
#pragma unroll
  for (int k2 = 0; k2 < 4; k2++) {
    const int kt = hh * 4 + k2;
    uint4 ov = make_uint4(
        h2u(o[2 * k2][0] * inv0, o[2 * k2][1] * inv0),
        h2u(o[2 * k2][2] * inv1, o[2 * k2][3] * inv1),
        h2u(o[2 * k2 + 1][0] * inv0, o[2 * k2 + 1][1] * inv0),
        h2u(o[2 * k2 + 1][2] * inv1, o[2 * k2 + 1][3] * inv1));
    *(uint4*)(pOut + (size_t)((mtile * 64 + kt) * 32 + lane) * 4) = ov;
  }
}

extern "C" void kernel_launch(void* const* d_in, const int* in_sizes, int n_in,
                              void* d_out, int out_size) {
  const float* x  = (const float*)d_in[0];
  const float* Wq = (const float*)d_in[1];
  const float* bq = (const float*)d_in[2];
  const float* Wk = (const float*)d_in[3];
  const float* bk = (const float*)d_in[4];
  const float* Wv = (const float*)d_in[5];
  const float* bv = (const float*)d_in[6];
  const float* Wo = (const float*)d_in[7];
  const float* bo = (const float*)d_in[8];
  float* out = (float*)d_out;

  uint32_t *qp, *kp, *ap, *xp, *wp;
  uint16_t *vtp;
  cudaGetSymbolAddress((void**)&qp, g_q);
  cudaGetSymbolAddress((void**)&kp, g_k);
  cudaGetSymbolAddress((void**)&vtp, g_vt);
  cudaGetSymbolAddress((void**)&ap, g_attp);
  cudaGetSymbolAddress((void**)&xp, g_xp);
  cudaGetSymbolAddress((void**)&wp, g_wp);

  static int attr_set = 0;
  if (!attr_set) {
    cudaFuncSetAttribute(gemm_fp16, cudaFuncAttributeMaxDynamicSharedMemorySize,
                         GEMM_SMEM);
    cudaFuncSetAttribute(attn5, cudaFuncAttributeMaxDynamicSharedMemorySize,
                         ATTN_SMEM);
    attr_set = 1;
  }

  const float QSCALE = 0.125f * 1.4426950408889634f;  // 1/sqrt(Dh) * log2(e)
  const size_t WSZ = (size_t)DM * DM / 2;             // words per packed W

  // 1) pack inputs into fp16 fragment layouts (coalesced)
  pack_all<<<dim3(512, 1, 5), 256>>>(x, Wq, Wk, Wv, Wo, xp, wp);

  // 2) fused QKV: Q,K -> fp16 rot (+Q scale); V -> fp16 transposed
  gemm_fp16<<<dim3(8, 32, 3), 256, GEMM_SMEM>>>(
      xp, wp, wp + WSZ, wp + 2 * WSZ, bq, bk, bv, qp, kp, vtp,
      2, 2, 3, QSCALE, 1.f, 1.f);

  // 3) attention (register-resident P) -> fp16 packed-A fragments
  attn5<<<dim3(16, 32), 256, ATTN_SMEM>>>(qp, kp, vtp, ap);

  // 4) output projection (fp32 out)
  gemm_fp16<<<dim3(8, 32, 1), 256, GEMM_SMEM>>>(
      ap, wp + 3 * WSZ, wp + 3 * WSZ, wp + 3 * WSZ, bo, bo, bo, out, out, out,
      0, 0, 0, 1.f, 1.f, 1.f);
}

// round 13
// speedup vs baseline: 8.0384x; 1.0234x over previous
#include <cuda_runtime.h>
#include <cuda_fp16.h>
#include <cstdint>

#define BB 2
#define TT 2048
#define DM 1024
#define NH 16
#define DH 64
#define MM (BB * TT)   // 4096

// Scratch (device globals; no allocation allowed)
__device__ uint32_t g_q[BB * NH * TT * (DH / 2)];   // fp16 [B,H,T,Dh], *0.125*log2e
__device__ uint32_t g_k[BB * NH * TT * (DH / 2)];   // fp16 [B,H,T,Dh]
__device__ uint16_t g_vt[BB * NH * DH * TT];        // fp16 [B,H,Dh,T] (transposed)
__device__ uint32_t g_attp[MM * DM / 2];            // attn out, fp16 packed-A frags
__device__ uint32_t g_xp[MM * DM / 2];              // x fp16 packed-A frags
__device__ uint32_t g_wp[4 * DM * DM / 2];          // W's fp16 packed-B frags

// ---------------------------------------------------------------------------
// helpers
// ---------------------------------------------------------------------------
__device__ __forceinline__ uint32_t smem_u32(const void* p) {
  uint32_t a;
  asm("{ .reg .u64 t; cvta.to.shared.u64 t, %1; cvt.u32.u64 %0, t; }"
      : "=r"(a) : "l"(p));
  return a;
}

__device__ __forceinline__ uint32_t h2u(float lo, float hi) {
  __half2 h = __floats2half2_rn(lo, hi);
  return *reinterpret_cast<uint32_t*>(&h);
}

// fp16 m16n8k16
__device__ __forceinline__ void mma16(float* c, const unsigned* a,
                                      unsigned b0, unsigned b1) {
  asm("mma.sync.aligned.m16n8k16.row.col.f32.f16.f16.f32 "
      "{%0,%1,%2,%3},{%4,%5,%6,%7},{%8,%9},{%0,%1,%2,%3};"
      : "+f"(c[0]), "+f"(c[1]), "+f"(c[2]), "+f"(c[3])
      : "r"(a[0]), "r"(a[1]), "r"(a[2]), "r"(a[3]), "r"(b0), "r"(b1));
}

#define CP_ASYNC16(dst, src) \
  asm volatile("cp.async.cg.shared.global [%0], [%1], 16;" :: "r"(dst), "l"(src))
#define CP_COMMIT() asm volatile("cp.async.commit_group;" ::: "memory")
#define CP_WAIT(n)  asm volatile("cp.async.wait_group %0;" :: "n"(n) : "memory")

// ---------------------------------------------------------------------------
// Packing into fp16 mma fragment order — coalesced (proven R11).
// ---------------------------------------------------------------------------
__global__ void pack_all(const float* __restrict__ x,
                         const float* __restrict__ Wq,
                         const float* __restrict__ Wk,
                         const float* __restrict__ Wv,
                         const float* __restrict__ Wo,
                         uint32_t* __restrict__ pX,
                         uint32_t* __restrict__ pW) {
  const int z = blockIdx.z;
  const int idx0 = blockIdx.x * blockDim.x + threadIdx.x;
  const int stride = gridDim.x * blockDim.x;
  if (z == 0) {
    for (int i = idx0; i < (MM / 16) * 64 * 32; i += stride) {
      int lane = i & 31, kt = (i >> 5) & 63, mt = i >> 11;
      int g7 = lane >> 2, t0 = lane & 3;
      const float* r0 = x + (size_t)(mt * 16 + g7) * DM + kt * 16 + 2 * t0;
      const float* r1 = r0 + 8 * DM;
      float2 a0 = *(const float2*)(r0);
      float2 a1 = *(const float2*)(r1);
      float2 a2 = *(const float2*)(r0 + 8);
      float2 a3 = *(const float2*)(r1 + 8);
      uint4 o = make_uint4(h2u(a0.x, a0.y), h2u(a1.x, a1.y),
                           h2u(a2.x, a2.y), h2u(a3.x, a3.y));
      *(uint4*)(pX + (size_t)((mt * 64 + kt) * 32 + lane) * 4) = o;
    }
  } else {
    const float* W = (z == 1) ? Wq : ((z == 2) ? Wk : ((z == 3) ? Wv : Wo));
    uint32_t* dst = pW + (size_t)(z - 1) * (DM * DM / 2);
    for (int i = idx0; i < (DM / 8) * 64 * 32; i += stride) {
      int lane = i & 31, kt = (i >> 5) & 63, nt = i >> 11;
      int g = lane >> 2, t0 = lane & 3;
      const float* rw = W + (size_t)(nt * 8 + g) * DM + kt * 16 + 2 * t0;
      float2 b0 = *(const float2*)(rw);
      float2 b1 = *(const float2*)(rw + 8);
      uint2 o = make_uint2(h2u(b0.x, b0.y), h2u(b1.x, b1.y));
      *(uint2*)(dst + (size_t)((nt * 64 + kt) * 64 + lane * 2)) = o;
    }
  }
}

// ---------------------------------------------------------------------------
// GEMM (fp16 m16n8k16): out = A[M,1024] @ W[1024,1024]^T + bias
// Block 128x128, 8 warps (2m x 4n), k-step 32, 4-stage cp.async. (proven R10)
// modes: 0 plain fp32 [M,DM]; 2 head-split+rotate -> fp16 [B,H,T,Dh] (*scale);
//        3 head-split -> fp16 transposed [B,H,Dh,T] via smem-staged
//        coalesced stores (FIXED: full 128-t coverage).
// ---------------------------------------------------------------------------
#define GSTG 16384
#define GEMM_SMEM (4 * GSTG)   // 65536

__global__ void __launch_bounds__(256, 2) gemm_fp16(
    const uint32_t* __restrict__ pA,
    const uint32_t* __restrict__ pB0, const uint32_t* __restrict__ pB1,
    const uint32_t* __restrict__ pB2,
    const float* __restrict__ bi0, const float* __restrict__ bi1,
    const float* __restrict__ bi2,
    void* __restrict__ o0, void* __restrict__ o1, void* __restrict__ o2,
    int md0, int md1, int md2, float sc0, float sc1, float sc2) {
  extern __shared__ __align__(16) char smem[];
  const int tid = threadIdx.x;
  const int w = tid >> 5, lane = tid & 31;
  const int r = lane >> 2, c = lane & 3;
  const int wm = w >> 2, wn = w & 3;
  const int z = blockIdx.z;
  const uint32_t* pB = (z == 0) ? pB0 : ((z == 1) ? pB1 : pB2);
  const float* bias = (z == 0) ? bi0 : ((z == 1) ? bi1 : bi2);
  void* out = (z == 0) ? o0 : ((z == 1) ? o1 : o2);
  const int mode = (z == 0) ? md0 : ((z == 1) ? md1 : md2);
  const float scale = (z == 0) ? sc0 : ((z == 1) ? sc1 : sc2);

  const char* Ab = (const char*)(pA + ((size_t)blockIdx.y << 16));
  const char* Bb = (const char*)(pB + ((size_t)blockIdx.x << 16));
  const uint32_t sb = smem_u32(smem);

  float acc[4][4][4] = {};

  auto load_iter = [&](int it, int s) {
    uint32_t sa = sb + s * GSTG;
    const int it2 = it * 2;
#pragma unroll
    for (int i = 0; i < 2; i++) {
      int cid = tid + i * 256;
      int mt = cid >> 6, ktl = (cid >> 5) & 1, off = cid & 31;
      CP_ASYNC16(sa + ((mt * 2 + ktl) * 32 + off) * 16,
                 Ab + ((size_t)(mt * 64 + it2 + ktl) * 32 + off) * 16);
    }
#pragma unroll
    for (int i = 0; i < 2; i++) {
      int cid = tid + i * 256;
      int nt = cid >> 5, ktl = (cid >> 4) & 1, off = cid & 15;
      CP_ASYNC16(sa + 8192 + ((nt * 2 + ktl) * 16 + off) * 16,
                 Bb + ((size_t)(nt * 64 + it2 + ktl) * 16 + off) * 16);
    }
    CP_COMMIT();
  };

  load_iter(0, 0);
  load_iter(1, 1);
  load_iter(2, 2);

  for (int it = 0; it < 32; it++) {
    CP_WAIT(2);
    __syncthreads();
    const int nx = it + 3;
    if (nx < 32) load_iter(nx, nx & 3); else CP_COMMIT();
    const char* st = smem + (it & 3) * GSTG;
#pragma unroll
    for (int ktl = 0; ktl < 2; ktl++) {
      uint2 bfr[4];
#pragma unroll
      for (int n = 0; n < 4; n++)
        bfr[n] = *(const uint2*)(st + 8192 +
                                 (((wn * 4 + n) * 2 + ktl) * 32 + lane) * 8);
      uint4 afr[4];
#pragma unroll
      for (int m = 0; m < 4; m++)
        afr[m] = *(const uint4*)(st +
                                 (((wm * 4 + m) * 2 + ktl) * 32 + lane) * 16);
#pragma unroll
      for (int n = 0; n < 4; n++)
#pragma unroll
        for (int m = 0; m < 4; m++)
          mma16(acc[m][n], (const unsigned*)&afr[m], bfr[n].x, bfr[n].y);
    }
  }

  if (mode == 3) {
    // V^T: stage fp16 [dh_local][t_local] tile in smem (272B rows), then
    // coalesced 16B stores along t.  Tile = 128 dh x 128 t (256B of data/row).
    CP_WAIT(0);
    __syncthreads();
#pragma unroll
    for (int m = 0; m < 4; m++) {
#pragma unroll
      for (int n = 0; n < 4; n++) {
        const int coll = (wn * 4 + n) * 8 + 2 * c;
        const int colg = blockIdx.x * 128 + coll;
        const float b0 = bias[colg], b1 = bias[colg + 1];
#pragma unroll
        for (int hf = 0; hf < 2; hf++) {
          const int rowl = (wm * 4 + m) * 16 + r + 8 * hf;
          __half h0 = __float2half_rn(acc[m][n][2 * hf] + b0);
          __half h1 = __float2half_rn(acc[m][n][2 * hf + 1] + b1);
          *(__half*)(smem + coll * 272 + rowl * 2) = h0;
          *(__half*)(smem + (coll + 1) * 272 + rowl * 2) = h1;
        }
      }
    }
    __syncthreads();
    uint16_t* vt = (uint16_t*)out;
    const int b_ = (blockIdx.y * 128) >> 11;
    const int t0g = (blockIdx.y * 128) & (TT - 1);
    // FIX: 128 dh-rows x 16 segs x 16B = full 128-t coverage (2048 ids)
#pragma unroll
    for (int i = 0; i < 8; i++) {
      int id = tid + i * 256;             // 0..2047
      int dhl = id >> 4, seg = id & 15;   // 128 dh-rows x 16 x 16B
      int colg = blockIdx.x * 128 + dhl;
      int h = colg >> 6, dh = colg & (DH - 1);
      uint4 v = *(const uint4*)(smem + dhl * 272 + seg * 16);
      *(uint4*)(vt + ((size_t)(b_ * NH + h) * DH + dh) * TT + t0g + seg * 8) = v;
    }
    return;
  }

  // epilogue (modes 0, 2)
#pragma unroll
  for (int m = 0; m < 4; m++) {
    const int row0 = blockIdx.y * 128 + (wm * 4 + m) * 16 + r;
#pragma unroll
    for (int n = 0; n < 4; n++) {
      const int col = blockIdx.x * 128 + (wn * 4 + n) * 8 + 2 * c;
      const float b0 = bias[col], b1 = bias[col + 1];
#pragma unroll
      for (int hf = 0; hf < 2; hf++) {
        const int row = row0 + 8 * hf;
        float v0 = acc[m][n][2 * hf] + b0;
        float v1 = acc[m][n][2 * hf + 1] + b1;
        if (mode == 0) {
          *(float2*)((float*)out + (size_t)row * DM + col) =
              make_float2(v0, v1);
        } else {  // mode 2: rotate_half + scale, fp16 [B,H,T,Dh]
          int b_ = row >> 11, t = row & (TT - 1);
          int h = col >> 6, dh = col & (DH - 1);
          float q0 = -v1 * scale, q1 = v0 * scale;
          ((uint32_t*)out)[((size_t)(b_ * NH + h) * TT + t) * 32 + (dh >> 1)] =
              h2u(q0, q1);
        }
      }
    }
  }
}

// ---------------------------------------------------------------------------
// Flash attention v6: fp16 mma, register-resident P (proven R11), with
// 128-key pipeline stages (two 64-key halves per fill) — half the syncs.
// smem: stage s at s*36864; half h at +h*18432: K 64x144B, V^T 64x144B.
// ---------------------------------------------------------------------------
#define HSTG 18432
#define STG128 36864
#define ATTN_SMEM (2 * STG128)   // 73728

__global__ void __launch_bounds__(256, 2) attn6(
    const uint32_t* __restrict__ Qw, const uint32_t* __restrict__ Kw,
    const uint16_t* __restrict__ Vt, uint32_t* __restrict__ pOut) {
  extern __shared__ __align__(16) char sm[];
  const uint32_t sb = smem_u32(sm);
  const int tid = threadIdx.x, w = tid >> 5, lane = tid & 31;
  const int r = lane >> 2, c = lane & 3;
  const int qb = gridDim.x - 1 - blockIdx.x;  // longest first
  const int bh = blockIdx.y;

  // fill 128 keys (two halves) into stage s
  auto fill = [&](int jt128, int s) {
    const uint32_t base = sb + s * STG128;
    const uint32_t* Kg = Kw + ((size_t)(bh * TT + jt128 * 128)) * 32;
    const uint16_t* Vg = Vt + (size_t)bh * DH * TT + jt128 * 128;
#pragma unroll
    for (int i = 0; i < 4; i++) {
      int id = tid + i * 256;           // 0..1023
      int row = id >> 3, sc = id & 7;   // 128 rows x 8 segs
      int half = row >> 6, rl = row & 63;
      CP_ASYNC16(base + half * HSTG + rl * 144 + sc * 16,
                 Kg + row * 32 + sc * 4);
    }
#pragma unroll
    for (int i = 0; i < 4; i++) {
      int id = tid + i * 256;           // 0..1023
      int sc = id & 7;
      int dh = (id >> 3) & 63, half = id >> 9;
      CP_ASYNC16(base + half * HSTG + 9216 + dh * 144 + sc * 16,
                 Vg + (size_t)dh * TT + half * 64 + sc * 8);
    }
    CP_COMMIT();
  };

  // Q A-fragments (fp16, pre-scaled): 4 k16 chunks x 4 regs
  const uint32_t* Qu = Qw + ((size_t)bh * TT + qb * 128 + 16 * w) * 32;
  unsigned qa[4][4];
#pragma unroll
  for (int kc = 0; kc < 4; kc++) {
    qa[kc][0] = Qu[r * 32 + 8 * kc + c];
    qa[kc][1] = Qu[(r + 8) * 32 + 8 * kc + c];
    qa[kc][2] = Qu[r * 32 + 8 * kc + c + 4];
    qa[kc][3] = Qu[(r + 8) * 32 + 8 * kc + c + 4];
  }

  float o[8][4] = {};
  float mrow[2] = {-1e30f, -1e30f}, lrow[2] = {0.f, 0.f};

  const int nkt = qb + 1;   // 128-key iterations
  fill(0, 0);

  for (int jt128 = 0; jt128 < nkt; jt128++) {
    const int s = jt128 & 1;
    __syncthreads();
    if (jt128 + 1 < nkt) {
      fill(jt128 + 1, s ^ 1);
      CP_WAIT(1);
    } else {
      CP_WAIT(0);
    }
    __syncthreads();

#pragma unroll
    for (int half = 0; half < 2; half++) {
      const int jt = 2 * jt128 + half;
      const char* kbuf = sm + s * STG128 + half * HSTG;
      const char* vbuf = kbuf + 9216;

      // S = Q @ K^T (log2 domain)
      float sacc[8][4] = {};
#pragma unroll
      for (int kc = 0; kc < 4; kc++) {
#pragma unroll
        for (int ni = 0; ni < 8; ni++) {
          const uint32_t* bp =
              (const uint32_t*)(kbuf + (8 * ni + r) * 144 + (8 * kc + c) * 4);
          mma16(sacc[ni], qa[kc], bp[0], bp[4]);
        }
      }

      if (jt >= 2 * qb) {  // diagonal tiles: causal mask
        const int qrow0 = qb * 128 + 16 * w + r;
#pragma unroll
        for (int ni = 0; ni < 8; ni++) {
          const int key0 = jt * 64 + 8 * ni + 2 * c;
#pragma unroll
          for (int reg = 0; reg < 4; reg++) {
            int key = key0 + (reg & 1);
            int qr = qrow0 + 8 * (reg >> 1);
            if (key > qr) sacc[ni][reg] = -1e30f;
          }
        }
      }

      // online softmax (base-2)
#pragma unroll
      for (int h = 0; h < 2; h++) {
        float mx = -1e30f;
#pragma unroll
        for (int ni = 0; ni < 8; ni++)
          mx = fmaxf(mx, fmaxf(sacc[ni][2 * h], sacc[ni][2 * h + 1]));
        mx = fmaxf(mx, __shfl_xor_sync(0xffffffffu, mx, 1));
        mx = fmaxf(mx, __shfl_xor_sync(0xffffffffu, mx, 2));
        float mnew = fmaxf(mrow[h], mx);
        float corr = exp2f(mrow[h] - mnew);
        mrow[h] = mnew;
        float rs = 0.f;
#pragma unroll
        for (int ni = 0; ni < 8; ni++) {
          sacc[ni][2 * h] = exp2f(sacc[ni][2 * h] - mnew);
          sacc[ni][2 * h + 1] = exp2f(sacc[ni][2 * h + 1] - mnew);
          rs += sacc[ni][2 * h] + sacc[ni][2 * h + 1];
        }
        rs += __shfl_xor_sync(0xffffffffu, rs, 1);
        rs += __shfl_xor_sync(0xffffffffu, rs, 2);
        lrow[h] = lrow[h] * corr + rs;
#pragma unroll
        for (int ni = 0; ni < 8; ni++) {
          o[ni][2 * h] *= corr;
          o[ni][2 * h + 1] *= corr;
        }
      }

      // O += P @ V (QK C-frag == PV A-frag; register-resident P)
#pragma unroll
      for (int kc = 0; kc < 4; kc++) {
        unsigned pa[4];
        pa[0] = h2u(sacc[2 * kc][0], sacc[2 * kc][1]);
        pa[1] = h2u(sacc[2 * kc][2], sacc[2 * kc][3]);
        pa[2] = h2u(sacc[2 * kc + 1][0], sacc[2 * kc + 1][1]);
        pa[3] = h2u(sacc[2 * kc + 1][2], sacc[2 * kc + 1][3]);
#pragma unroll
        for (int ni = 0; ni < 8; ni++) {
          const uint32_t* vp =
              (const uint32_t*)(vbuf + (8 * ni + r) * 144 + (8 * kc + c) * 4);
          mma16(o[ni], pa, vp[0], vp[4]);
        }
      }
    }
  }

  // epilogue: normalize, fp16 packed-A fragments, uint4 stores (proven R11)
  const int b_ = bh >> 4, hh = bh & (NH - 1);
  const int mtile = b_ * 128 + qb * 8 + w;
  const float inv0 = 1.0f / lrow[0], inv1 = 1.0f / lrow[1];
#pragma unroll
  for (int k2 = 0; k2 < 4; k2++) {
    const int kt = hh * 4 + k2;
    uint4 ov = make_uint4(
        h2u(o[2 * k2][0] * inv0, o[2 * k2][1] * inv0),
        h2u(o[2 * k2][2] * inv1, o[2 * k2][3] * inv1),
        h2u(o[2 * k2 + 1][0] * inv0, o[2 * k2 + 1][1] * inv0),
        h2u(o[2 * k2 + 1][2] * inv1, o[2 * k2 + 1][3] * inv1));
    *(uint4*)(pOut + (size_t)((mtile * 64 + kt) * 32 + lane) * 4) = ov;
  }
}

extern "C" void kernel_launch(void* const* d_in, const int* in_sizes, int n_in,
                              void* d_out, int out_size) {
  const float* x  = (const float*)d_in[0];
  const float* Wq = (const float*)d_in[1];
  const float* bq = (const float*)d_in[2];
  const float* Wk = (const float*)d_in[3];
  const float* bk = (const float*)d_in[4];
  const float* Wv = (const float*)d_in[5];
  const float* bv = (const float*)d_in[6];
  const float* Wo = (const float*)d_in[7];
  const float* bo = (const float*)d_in[8];
  float* out = (float*)d_out;

  uint32_t *qp, *kp, *ap, *xp, *wp;
  uint16_t *vtp;
  cudaGetSymbolAddress((void**)&qp, g_q);
  cudaGetSymbolAddress((void**)&kp, g_k);
  cudaGetSymbolAddress((void**)&vtp, g_vt);
  cudaGetSymbolAddress((void**)&ap, g_attp);
  cudaGetSymbolAddress((void**)&xp, g_xp);
  cudaGetSymbolAddress((void**)&wp, g_wp);

  static int attr_set = 0;
  if (!attr_set) {
    cudaFuncSetAttribute(gemm_fp16, cudaFuncAttributeMaxDynamicSharedMemorySize,
                         GEMM_SMEM);
    cudaFuncSetAttribute(attn6, cudaFuncAttributeMaxDynamicSharedMemorySize,
                         ATTN_SMEM);
    attr_set = 1;
  }

  const float QSCALE = 0.125f * 1.4426950408889634f;  // 1/sqrt(Dh) * log2(e)
  const size_t WSZ = (size_t)DM * DM / 2;             // words per packed W

  // 1) pack inputs into fp16 fragment layouts (coalesced)
  pack_all<<<dim3(512, 1, 5), 256>>>(x, Wq, Wk, Wv, Wo, xp, wp);

  // 2) fused QKV: Q,K -> fp16 rot (+Q scale); V -> fp16 transposed (staged)
  gemm_fp16<<<dim3(8, 32, 3), 256, GEMM_SMEM>>>(
      xp, wp, wp + WSZ, wp + 2 * WSZ, bq, bk, bv, qp, kp, vtp,
      2, 2, 3, QSCALE, 1.f, 1.f);

  // 3) attention (128-key stages, register-resident P)
  attn6<<<dim3(16, 32), 256, ATTN_SMEM>>>(qp, kp, vtp, ap);

  // 4) output projection (fp32 out)
  gemm_fp16<<<dim3(8, 32, 1), 256, GEMM_SMEM>>>(
      ap, wp + 3 * WSZ, wp + 3 * WSZ, wp + 3 * WSZ, bo, bo, bo, out, out, out,
      0, 0, 0, 1.f, 1.f, 1.f);
}